// round 2
// baseline (speedup 1.0000x reference)
#include <cuda_runtime.h>
#include <cstdint>

#define N_NODES 50000
#define N_EDGES 600000
#define N_RELS  500
#define DIM     128
#define TILE_R  64

typedef unsigned long long u64;

// ---------------------------------------------------------------------------
// Device scratch (no allocations allowed)
// ---------------------------------------------------------------------------
__device__ float g_S[(size_t)N_NODES * DIM];   // normalized aggregated messages
__device__ int   g_cnt[N_NODES];               // per-dst edge counts
__device__ int   g_off[N_NODES + 1];           // CSR offsets
__device__ int   g_cur[N_NODES];               // fill cursors
__device__ int   g_ep[N_EDGES];                // packed (src | type<<17)

// ---------------------------------------------------------------------------
// Kernel 1: zero counts
// ---------------------------------------------------------------------------
__global__ void zero_cnt_kernel() {
    int i = blockIdx.x * blockDim.x + threadIdx.x;
    if (i < N_NODES) g_cnt[i] = 0;
}

// ---------------------------------------------------------------------------
// Kernel 2: histogram of edge_dst
// ---------------------------------------------------------------------------
__global__ void hist_kernel(const int* __restrict__ edge_dst) {
    int e = blockIdx.x * blockDim.x + threadIdx.x;
    if (e < N_EDGES) atomicAdd(&g_cnt[edge_dst[e]], 1);
}

// ---------------------------------------------------------------------------
// Kernel 3: single-block exclusive scan over 50000 counts
// ---------------------------------------------------------------------------
__global__ void __launch_bounds__(1024) scan_kernel() {
    __shared__ int warpsum[32];
    const int CH = (N_NODES + 1023) / 1024;   // 49
    int t    = threadIdx.x;
    int lane = t & 31;
    int w    = t >> 5;
    int beg  = t * CH;
    int end  = beg + CH; if (end > N_NODES) end = N_NODES;
    if (beg > N_NODES) beg = N_NODES;

    int s = 0;
    for (int i = beg; i < end; i++) s += g_cnt[i];

    // warp inclusive scan
    int v = s;
#pragma unroll
    for (int o = 1; o < 32; o <<= 1) {
        int u = __shfl_up_sync(0xFFFFFFFFu, v, o);
        if (lane >= o) v += u;
    }
    if (lane == 31) warpsum[w] = v;
    __syncthreads();
    if (w == 0) {
        int x = warpsum[lane];
#pragma unroll
        for (int o = 1; o < 32; o <<= 1) {
            int u = __shfl_up_sync(0xFFFFFFFFu, x, o);
            if (lane >= o) x += u;
        }
        warpsum[lane] = x;
    }
    __syncthreads();

    int excl = v - s + (w > 0 ? warpsum[w - 1] : 0);
    int run = excl;
    for (int i = beg; i < end; i++) {
        g_off[i] = run;
        g_cur[i] = run;
        run += g_cnt[i];
    }
    if (t == 1023) g_off[N_NODES] = run;
}

// ---------------------------------------------------------------------------
// Kernel 4: fill CSR edge payloads
// ---------------------------------------------------------------------------
__global__ void fill_kernel(const int* __restrict__ edge_src,
                            const int* __restrict__ edge_dst,
                            const int* __restrict__ edge_type) {
    int e = blockIdx.x * blockDim.x + threadIdx.x;
    if (e >= N_EDGES) return;
    int d   = edge_dst[e];
    int pos = atomicAdd(&g_cur[d], 1);
    g_ep[pos] = edge_src[e] | (edge_type[e] << 17);
}

// ---------------------------------------------------------------------------
// Kernel 5: gather.  One warp per node:
//   S[d] = norm[d] * sum_{e: dst==d} (h[src_e] + rel_emb[type_e])
// ---------------------------------------------------------------------------
__global__ void __launch_bounds__(256) gather_kernel(
    const float* __restrict__ h,
    const float* __restrict__ rel_emb,
    const float* __restrict__ norm)
{
    int node = blockIdx.x * 8 + (threadIdx.x >> 5);
    int lane = threadIdx.x & 31;
    if (node >= N_NODES) return;

    int beg = g_off[node];
    int end = g_off[node + 1];

    float4 acc = make_float4(0.f, 0.f, 0.f, 0.f);
#pragma unroll 2
    for (int j = beg; j < end; j++) {
        int p = __ldg(g_ep + j);            // broadcast within warp
        int s = p & 0x1FFFF;
        int t = p >> 17;
        float4 hv = *(const float4*)(h       + (size_t)s * DIM + lane * 4);
        float4 rv = *(const float4*)(rel_emb + (size_t)t * DIM + lane * 4);
        acc.x += hv.x + rv.x;
        acc.y += hv.y + rv.y;
        acc.z += hv.z + rv.z;
        acc.w += hv.w + rv.w;
    }
    float nm = __ldg(norm + node);
    acc.x *= nm; acc.y *= nm; acc.z *= nm; acc.w *= nm;
    *(float4*)(g_S + (size_t)node * DIM + lane * 4) = acc;
}

// ---------------------------------------------------------------------------
// Kernel 6: fused epilogue GEMM with packed f32x2 FMA.
//   out = relu( S @ W_neighbor + h @ loop_weight )     (S already norm-scaled)
// 256 threads, 64 rows/block, 8 rows x 4 cols per thread.
// Accumulators are packed f32x2 pairs over columns; b-pairs are direct LDS.64.
// ---------------------------------------------------------------------------
__device__ __forceinline__ void fma2(u64& acc, u64 a, u64 b) {
    asm("fma.rn.f32x2 %0, %1, %2, %0;" : "+l"(acc) : "l"(a), "l"(b));
}
__device__ __forceinline__ u64 packdup(float a) {
    u64 r;
    asm("mov.b64 %0, {%1, %1};" : "=l"(r) : "f"(a));
    return r;
}

__global__ void __launch_bounds__(256) fused_gemm_kernel(
    const float* __restrict__ h,
    const float* __restrict__ W_neighbor,
    const float* __restrict__ loop_weight,
    float* __restrict__ out)
{
    extern __shared__ float smem[];
    float* sW = smem;                 // DIM*DIM floats (64KB)
    float* sA = smem + DIM * DIM;     // TILE_R*DIM floats (32KB)

    const int tid  = threadIdx.x;
    const int warp = tid >> 5;
    const int lane = tid & 31;
    const int row0 = blockIdx.x * TILE_R;

    u64 acc[8][2];
#pragma unroll
    for (int i = 0; i < 8; i++) { acc[i][0] = 0ull; acc[i][1] = 0ull; }

    for (int pass = 0; pass < 2; pass++) {
        const float* W   = pass == 0 ? W_neighbor : loop_weight;
        const float* src = pass == 0 ? g_S        : h;

        if (pass) __syncthreads();
        // stage W
        {
            const float4* W4  = (const float4*)W;
            float4*       sW4 = (float4*)sW;
            for (int i = tid; i < DIM * DIM / 4; i += 256) sW4[i] = W4[i];
        }
        // stage A
        for (int i = tid; i < TILE_R * (DIM / 4); i += 256) {
            int r  = i / (DIM / 4);
            int c  = i % (DIM / 4);
            int gr = row0 + r;
            float4 v = make_float4(0.f, 0.f, 0.f, 0.f);
            if (gr < N_NODES) v = ((const float4*)(src + (size_t)gr * DIM))[c];
            ((float4*)(sA + r * DIM))[c] = v;
        }
        __syncthreads();

        const float* arow = sA + warp * 8 * DIM;
        const float* bcol = sW + lane * 4;
#pragma unroll 4
        for (int k = 0; k < DIM; k++) {
            u64 b0 = *(const u64*)(bcol + k * DIM);
            u64 b1 = *(const u64*)(bcol + k * DIM + 2);
#pragma unroll
            for (int i = 0; i < 8; i++) {
                u64 a = packdup(arow[i * DIM + k]);
                fma2(acc[i][0], a, b0);
                fma2(acc[i][1], a, b1);
            }
        }
    }

    // epilogue: unpack, relu, store
#pragma unroll
    for (int i = 0; i < 8; i++) {
        int gr = row0 + warp * 8 + i;
        if (gr < N_NODES) {
            float x, y, z, w;
            asm("mov.b64 {%0, %1}, %2;" : "=f"(x), "=f"(y) : "l"(acc[i][0]));
            asm("mov.b64 {%0, %1}, %2;" : "=f"(z), "=f"(w) : "l"(acc[i][1]));
            float4 v;
            v.x = fmaxf(x, 0.f);
            v.y = fmaxf(y, 0.f);
            v.z = fmaxf(z, 0.f);
            v.w = fmaxf(w, 0.f);
            ((float4*)(out + (size_t)gr * DIM))[lane] = v;
        }
    }
}

// ---------------------------------------------------------------------------
// Launcher
// ---------------------------------------------------------------------------
extern "C" void kernel_launch(void* const* d_in, const int* in_sizes, int n_in,
                              void* d_out, int out_size)
{
    (void)in_sizes; (void)n_in; (void)out_size;

    const float* h          = (const float*)d_in[0];
    const float* norm       = (const float*)d_in[1];
    const float* rel_emb    = (const float*)d_in[2];
    const float* W_neighbor = (const float*)d_in[3];
    const float* loop_w     = (const float*)d_in[4];
    const int*   edge_src   = (const int*)d_in[5];
    const int*   edge_dst   = (const int*)d_in[6];
    const int*   edge_type  = (const int*)d_in[7];
    float*       out        = (float*)d_out;

    zero_cnt_kernel<<<(N_NODES + 255) / 256, 256>>>();
    hist_kernel<<<(N_EDGES + 255) / 256, 256>>>(edge_dst);
    scan_kernel<<<1, 1024>>>();
    fill_kernel<<<(N_EDGES + 255) / 256, 256>>>(edge_src, edge_dst, edge_type);
    gather_kernel<<<(N_NODES + 7) / 8, 256>>>(h, rel_emb, norm);

    {
        const int smem_bytes = (DIM * DIM + TILE_R * DIM) * (int)sizeof(float); // 96KB
        cudaFuncSetAttribute(fused_gemm_kernel,
                             cudaFuncAttributeMaxDynamicSharedMemorySize, smem_bytes);
        int blocks = (N_NODES + TILE_R - 1) / TILE_R;
        fused_gemm_kernel<<<blocks, 256, smem_bytes>>>(h, W_neighbor, loop_w, out);
    }
}

// round 4
// speedup vs baseline: 1.5447x; 1.5447x over previous
#include <cuda_runtime.h>
#include <cuda_bf16.h>
#include <cstdint>

#define N_NODES 50000
#define N_EDGES 600000
#define DIM     128

typedef unsigned int u32;
typedef unsigned short u16;

// ---------------------------------------------------------------------------
// Device scratch
// ---------------------------------------------------------------------------
__device__ float g_S[(size_t)N_NODES * DIM];                  // scatter accumulator
__device__ __align__(16) u16 g_Bh[256 * DIM];                 // B = [Wn;Wl] bf16 hi, [K=256][N=128]
__device__ __align__(16) u16 g_Bl[256 * DIM];                 // bf16 lo (residual)

// ---------------------------------------------------------------------------
// Kernel 1: zero scatter accumulator
// ---------------------------------------------------------------------------
__global__ void zero_S_kernel() {
    size_t i = (size_t)blockIdx.x * blockDim.x + threadIdx.x;
    if (i < (size_t)N_NODES * DIM / 4)
        ((float4*)g_S)[i] = make_float4(0.f, 0.f, 0.f, 0.f);
}

// ---------------------------------------------------------------------------
// Kernel 2: edge scatter (one warp per edge) — proven R1 version
// ---------------------------------------------------------------------------
__global__ void __launch_bounds__(256) scatter_edges_kernel(
    const float* __restrict__ h,
    const float* __restrict__ rel_emb,
    const int*   __restrict__ edge_src,
    const int*   __restrict__ edge_dst,
    const int*   __restrict__ edge_type)
{
    int warp = (int)((blockIdx.x * (unsigned)blockDim.x + threadIdx.x) >> 5);
    int lane = threadIdx.x & 31;
    if (warp >= N_EDGES) return;

    int s = __ldg(edge_src  + warp);
    int d = __ldg(edge_dst  + warp);
    int t = __ldg(edge_type + warp);

    const float4 hv = *(const float4*)(h       + (size_t)s * DIM + lane * 4);
    const float4 rv = *(const float4*)(rel_emb + (size_t)t * DIM + lane * 4);

    float4 m = make_float4(hv.x + rv.x, hv.y + rv.y, hv.z + rv.z, hv.w + rv.w);
    float* outp = g_S + (size_t)d * DIM + lane * 4;
    asm volatile("red.global.add.v4.f32 [%0], {%1, %2, %3, %4};"
                 :: "l"(outp), "f"(m.x), "f"(m.y), "f"(m.z), "f"(m.w) : "memory");
}

// ---------------------------------------------------------------------------
// Kernel 3: prep B = concat(W_neighbor, loop_weight) as bf16 hi/lo, [K][N].
// ---------------------------------------------------------------------------
__global__ void prep_B_kernel(const float* __restrict__ W_neighbor,
                              const float* __restrict__ loop_weight)
{
    int i = blockIdx.x * blockDim.x + threadIdx.x;   // 256*128 = 32768
    if (i >= 256 * DIM) return;
    int k = i >> 7;
    int n = i & 127;
    float w = (k < 128) ? W_neighbor[(size_t)k * DIM + n]
                        : loop_weight[(size_t)(k - 128) * DIM + n];
    __nv_bfloat16 hi = __float2bfloat16_rn(w);
    __nv_bfloat16 lo = __float2bfloat16_rn(w - __bfloat162float(hi));
    g_Bh[i] = __bfloat16_as_ushort(hi);
    g_Bl[i] = __bfloat16_as_ushort(lo);
}

// ---------------------------------------------------------------------------
// Kernel 4: fused tensor-core GEMM (mma.sync bf16, 3-product compensation)
//   out = relu( [norm*S | h] @ [Wn; Wl] )
// CTA: 256 threads (8 warps), tile M=128 x N=128, K staged in 4 chunks of 64.
// Warp tile 64x32.  Smem rows padded to kill ldmatrix bank conflicts.
// ---------------------------------------------------------------------------
#define A_LDS 72      // bf16 per A smem row (64 data + 8 pad) -> 144B stride
#define B_LDS 136     // bf16 per B smem row (128 data + 8 pad) -> 272B stride
#define SM_A_HI 0
#define SM_A_LO 18432
#define SM_B_HI 36864
#define SM_B_LO 54272
#define SM_TOTAL 71680

__device__ __forceinline__ void ldsm4(u32* r, u32 addr) {
    asm volatile("ldmatrix.sync.aligned.m8n8.x4.shared.b16 {%0,%1,%2,%3}, [%4];"
                 : "=r"(r[0]), "=r"(r[1]), "=r"(r[2]), "=r"(r[3]) : "r"(addr));
}
__device__ __forceinline__ void ldsm4t(u32* r, u32 addr) {
    asm volatile("ldmatrix.sync.aligned.m8n8.x4.trans.shared.b16 {%0,%1,%2,%3}, [%4];"
                 : "=r"(r[0]), "=r"(r[1]), "=r"(r[2]), "=r"(r[3]) : "r"(addr));
}
__device__ __forceinline__ void mma16816(float* d, const u32* a, u32 b0, u32 b1) {
    asm volatile("mma.sync.aligned.m16n8k16.row.col.f32.bf16.bf16.f32 "
                 "{%0,%1,%2,%3}, {%4,%5,%6,%7}, {%8,%9}, {%0,%1,%2,%3};"
                 : "+f"(d[0]), "+f"(d[1]), "+f"(d[2]), "+f"(d[3])
                 : "r"(a[0]), "r"(a[1]), "r"(a[2]), "r"(a[3]), "r"(b0), "r"(b1));
}

__global__ void __launch_bounds__(256, 1) gemm_mma_kernel(
    const float* __restrict__ h,
    const float* __restrict__ norm,
    float* __restrict__ out)
{
    extern __shared__ char smem[];
    u32 sbase;
    asm("{ .reg .u64 t; cvta.to.shared.u64 t, %1; cvt.u32.u64 %0, t; }"
        : "=r"(sbase) : "l"(smem));

    const int tid    = threadIdx.x;
    const int wid    = tid >> 5;
    const int lane   = tid & 31;
    const int warp_m = wid & 1;          // 0,1 -> 64-row halves
    const int warp_n = wid >> 1;         // 0..3 -> 32-col strips
    const int row0   = blockIdx.x * 128;

    float acc[4][4][4];
#pragma unroll
    for (int mi = 0; mi < 4; mi++)
#pragma unroll
        for (int ni = 0; ni < 4; ni++)
#pragma unroll
            for (int q = 0; q < 4; q++) acc[mi][ni][q] = 0.f;

    for (int c = 0; c < 4; c++) {
        if (c) __syncthreads();
        // ---- stage A chunk: 128 rows x 64 K, f32 -> bf16 hi/lo ----
        for (int i = tid; i < 1024; i += 256) {
            int r  = i >> 3;
            int kg = i & 7;              // 8 els
            int gr = row0 + r;
            float vals[8];
            if (gr < N_NODES) {
                const float* src;
                float scale;
                if (c < 2) { src = g_S + (size_t)gr * DIM + c * 64 + kg * 8;       scale = __ldg(norm + gr); }
                else       { src = h   + (size_t)gr * DIM + (c - 2) * 64 + kg * 8; scale = 1.f; }
                float4 v0 = *(const float4*)src;
                float4 v1 = *(const float4*)(src + 4);
                vals[0] = v0.x * scale; vals[1] = v0.y * scale;
                vals[2] = v0.z * scale; vals[3] = v0.w * scale;
                vals[4] = v1.x * scale; vals[5] = v1.y * scale;
                vals[6] = v1.z * scale; vals[7] = v1.w * scale;
            } else {
#pragma unroll
                for (int j = 0; j < 8; j++) vals[j] = 0.f;
            }
            u32 hiw[4], low[4];
#pragma unroll
            for (int p = 0; p < 4; p++) {
                __nv_bfloat16 h0 = __float2bfloat16_rn(vals[2 * p]);
                __nv_bfloat16 h1 = __float2bfloat16_rn(vals[2 * p + 1]);
                __nv_bfloat16 l0 = __float2bfloat16_rn(vals[2 * p]     - __bfloat162float(h0));
                __nv_bfloat16 l1 = __float2bfloat16_rn(vals[2 * p + 1] - __bfloat162float(h1));
                hiw[p] = (u32)__bfloat16_as_ushort(h0) | ((u32)__bfloat16_as_ushort(h1) << 16);
                low[p] = (u32)__bfloat16_as_ushort(l0) | ((u32)__bfloat16_as_ushort(l1) << 16);
            }
            u32 off = (u32)(r * (A_LDS * 2) + kg * 16);
            *(uint4*)(smem + SM_A_HI + off) = make_uint4(hiw[0], hiw[1], hiw[2], hiw[3]);
            *(uint4*)(smem + SM_A_LO + off) = make_uint4(low[0], low[1], low[2], low[3]);
        }
        // ---- stage B chunk: 64 K-rows x 128 N (bf16 already) ----
        for (int i = tid; i < 1024; i += 256) {
            int r = i >> 4;
            int j = i & 15;              // 16B = 8 bf16
            u32 off = (u32)(r * (B_LDS * 2) + j * 16);
            *(uint4*)(smem + SM_B_HI + off) = ((const uint4*)g_Bh)[(size_t)(c * 64 + r) * 16 + j];
            *(uint4*)(smem + SM_B_LO + off) = ((const uint4*)g_Bl)[(size_t)(c * 64 + r) * 16 + j];
        }
        __syncthreads();

        // ---- mainloop: 4 k16 steps ----
#pragma unroll
        for (int k16 = 0; k16 < 4; k16++) {
            u32 bh[2][4], bl[2][4];
#pragma unroll
            for (int ng = 0; ng < 2; ng++) {
                u32 baddr = sbase + SM_B_HI
                          + (u32)((k16 * 16 + (lane & 15)) * (B_LDS * 2))
                          + (u32)((warp_n * 32 + ng * 16 + (lane >> 4) * 8) * 2);
                ldsm4t(bh[ng], baddr);
                ldsm4t(bl[ng], baddr + (SM_B_LO - SM_B_HI));
            }
#pragma unroll
            for (int mi = 0; mi < 4; mi++) {
                u32 aaddr = sbase + SM_A_HI
                          + (u32)((warp_m * 64 + mi * 16 + (lane & 15)) * (A_LDS * 2))
                          + (u32)(k16 * 32 + (lane >> 4) * 16);
                u32 ah[4], al[4];
                ldsm4(ah, aaddr);
                ldsm4(al, aaddr + (SM_A_LO - SM_A_HI));
#pragma unroll
                for (int ni = 0; ni < 4; ni++) {
                    int ng = ni >> 1;
                    int hf = (ni & 1) * 2;
                    mma16816(acc[mi][ni], ah, bh[ng][hf], bh[ng][hf + 1]);
                    mma16816(acc[mi][ni], al, bh[ng][hf], bh[ng][hf + 1]);
                    mma16816(acc[mi][ni], ah, bl[ng][hf], bl[ng][hf + 1]);
                }
            }
        }
    }

    // ---- epilogue: relu + store ----
#pragma unroll
    for (int mi = 0; mi < 4; mi++) {
        int r0 = row0 + warp_m * 64 + mi * 16 + (lane >> 2);
#pragma unroll
        for (int ni = 0; ni < 4; ni++) {
            int col = warp_n * 32 + ni * 8 + (lane & 3) * 2;
            if (r0 < N_NODES) {
                float2 v;
                v.x = fmaxf(acc[mi][ni][0], 0.f);
                v.y = fmaxf(acc[mi][ni][1], 0.f);
                *(float2*)(out + (size_t)r0 * DIM + col) = v;
            }
            if (r0 + 8 < N_NODES) {
                float2 v;
                v.x = fmaxf(acc[mi][ni][2], 0.f);
                v.y = fmaxf(acc[mi][ni][3], 0.f);
                *(float2*)(out + (size_t)(r0 + 8) * DIM + col) = v;
            }
        }
    }
}

// ---------------------------------------------------------------------------
// Launcher
// ---------------------------------------------------------------------------
extern "C" void kernel_launch(void* const* d_in, const int* in_sizes, int n_in,
                              void* d_out, int out_size)
{
    (void)in_sizes; (void)n_in; (void)out_size;

    const float* h          = (const float*)d_in[0];
    const float* norm       = (const float*)d_in[1];
    const float* rel_emb    = (const float*)d_in[2];
    const float* W_neighbor = (const float*)d_in[3];
    const float* loop_w     = (const float*)d_in[4];
    const int*   edge_src   = (const int*)d_in[5];
    const int*   edge_dst   = (const int*)d_in[6];
    const int*   edge_type  = (const int*)d_in[7];
    float*       out        = (float*)d_out;

    prep_B_kernel<<<(256 * DIM + 255) / 256, 256>>>(W_neighbor, loop_w);
    {
        int n4 = N_NODES * DIM / 4;
        zero_S_kernel<<<(n4 + 255) / 256, 256>>>();
    }
    {
        long long total = (long long)N_EDGES * 32;
        scatter_edges_kernel<<<(int)((total + 255) / 256), 256>>>(h, rel_emb, edge_src, edge_dst, edge_type);
    }
    {
        static bool attr_set = false;
        if (!attr_set) {
            cudaFuncSetAttribute(gemm_mma_kernel,
                                 cudaFuncAttributeMaxDynamicSharedMemorySize, SM_TOTAL);
            attr_set = true;
        }
        int blocks = (N_NODES + 127) / 128;
        gemm_mma_kernel<<<blocks, 256, SM_TOTAL>>>(h, norm, out);
    }
}

// round 5
// speedup vs baseline: 1.6178x; 1.0473x over previous
#include <cuda_runtime.h>
#include <cuda_bf16.h>
#include <cstdint>

#define N_NODES 50000
#define N_EDGES 600000
#define DIM     128
#define M_PAD   50048
#define NTILES  391          // ceil(50000/128)
#define GRID_G  131          // ceil(391/3), 3 tiles per CTA

typedef unsigned int u32;
typedef unsigned short u16;

// ---------------------------------------------------------------------------
// Device scratch
// ---------------------------------------------------------------------------
__device__ float g_S[(size_t)N_NODES * DIM];                  // scatter accumulator
__device__ __align__(16) u16 g_Bh[256 * DIM];                 // B=[Wn;Wl] bf16 hi [K=256][N=128]
__device__ __align__(16) u16 g_Bl[256 * DIM];                 // bf16 lo
__device__ __align__(16) u16 g_Ah[(size_t)M_PAD * 256];       // A=[norm*S | h] bf16 hi [M][K=256]
__device__ __align__(16) u16 g_Al[(size_t)M_PAD * 256];       // bf16 lo

// ---------------------------------------------------------------------------
// Kernel 1: zero scatter accumulator
// ---------------------------------------------------------------------------
__global__ void zero_S_kernel() {
    size_t i = (size_t)blockIdx.x * blockDim.x + threadIdx.x;
    if (i < (size_t)N_NODES * DIM / 4)
        ((float4*)g_S)[i] = make_float4(0.f, 0.f, 0.f, 0.f);
}

// ---------------------------------------------------------------------------
// Kernel 2: edge scatter (one warp per edge) — proven R1 version
// ---------------------------------------------------------------------------
__global__ void __launch_bounds__(256) scatter_edges_kernel(
    const float* __restrict__ h,
    const float* __restrict__ rel_emb,
    const int*   __restrict__ edge_src,
    const int*   __restrict__ edge_dst,
    const int*   __restrict__ edge_type)
{
    int warp = (int)((blockIdx.x * (unsigned)blockDim.x + threadIdx.x) >> 5);
    int lane = threadIdx.x & 31;
    if (warp >= N_EDGES) return;

    int s = __ldg(edge_src  + warp);
    int d = __ldg(edge_dst  + warp);
    int t = __ldg(edge_type + warp);

    const float4 hv = *(const float4*)(h       + (size_t)s * DIM + lane * 4);
    const float4 rv = *(const float4*)(rel_emb + (size_t)t * DIM + lane * 4);

    float4 m = make_float4(hv.x + rv.x, hv.y + rv.y, hv.z + rv.z, hv.w + rv.w);
    float* outp = g_S + (size_t)d * DIM + lane * 4;
    asm volatile("red.global.add.v4.f32 [%0], {%1, %2, %3, %4};"
                 :: "l"(outp), "f"(m.x), "f"(m.y), "f"(m.z), "f"(m.w) : "memory");
}

// ---------------------------------------------------------------------------
// Kernel 3: prep B = concat(W_neighbor, loop_weight) bf16 hi/lo, [K][N]
// ---------------------------------------------------------------------------
__global__ void prep_B_kernel(const float* __restrict__ W_neighbor,
                              const float* __restrict__ loop_weight)
{
    int i = blockIdx.x * blockDim.x + threadIdx.x;
    if (i >= 256 * DIM) return;
    int k = i >> 7;
    int n = i & 127;
    float w = (k < 128) ? W_neighbor[(size_t)k * DIM + n]
                        : loop_weight[(size_t)(k - 128) * DIM + n];
    __nv_bfloat16 hi = __float2bfloat16_rn(w);
    __nv_bfloat16 lo = __float2bfloat16_rn(w - __bfloat162float(hi));
    g_Bh[i] = __bfloat16_as_ushort(hi);
    g_Bl[i] = __bfloat16_as_ushort(lo);
}

// ---------------------------------------------------------------------------
// Kernel 4: convert A = [norm*S | h] to bf16 hi/lo (pads rows >= N_NODES)
// One thread per 8 elements.
// ---------------------------------------------------------------------------
__global__ void __launch_bounds__(256) convert_A_kernel(
    const float* __restrict__ h,
    const float* __restrict__ norm)
{
    int i = blockIdx.x * blockDim.x + threadIdx.x;
    if (i >= M_PAD * 32) return;
    int row = i >> 5;
    int seg = i & 31;          // 32 segs of 8 elements over K=256

    float vals[8];
    if (row < N_NODES) {
        const float* src;
        float sc;
        if (seg < 16) { src = g_S + (size_t)row * DIM + seg * 8;        sc = __ldg(norm + row); }
        else          { src = h   + (size_t)row * DIM + (seg - 16) * 8; sc = 1.f; }
        float4 a = ((const float4*)src)[0];
        float4 b = ((const float4*)src)[1];
        vals[0] = a.x * sc; vals[1] = a.y * sc; vals[2] = a.z * sc; vals[3] = a.w * sc;
        vals[4] = b.x * sc; vals[5] = b.y * sc; vals[6] = b.z * sc; vals[7] = b.w * sc;
    } else {
#pragma unroll
        for (int j = 0; j < 8; j++) vals[j] = 0.f;
    }

    u32 hiw[4], low[4];
#pragma unroll
    for (int p = 0; p < 4; p++) {
        __nv_bfloat16 h0 = __float2bfloat16_rn(vals[2 * p]);
        __nv_bfloat16 h1 = __float2bfloat16_rn(vals[2 * p + 1]);
        __nv_bfloat16 l0 = __float2bfloat16_rn(vals[2 * p]     - __bfloat162float(h0));
        __nv_bfloat16 l1 = __float2bfloat16_rn(vals[2 * p + 1] - __bfloat162float(h1));
        hiw[p] = (u32)__bfloat16_as_ushort(h0) | ((u32)__bfloat16_as_ushort(h1) << 16);
        low[p] = (u32)__bfloat16_as_ushort(l0) | ((u32)__bfloat16_as_ushort(l1) << 16);
    }
    size_t v4 = (size_t)row * 32 + seg;
    ((uint4*)g_Ah)[v4] = make_uint4(hiw[0], hiw[1], hiw[2], hiw[3]);
    ((uint4*)g_Al)[v4] = make_uint4(low[0], low[1], low[2], low[3]);
}

// ---------------------------------------------------------------------------
// Kernel 5: pipelined tensor-core GEMM.
//   out = relu( A @ B ),  A = [norm*S | h] (bf16 hi/lo), B resident in smem.
// 131 CTAs x 3 M-tiles.  A chunks (64-K) double-buffered via cp.async.
// ---------------------------------------------------------------------------
#define A_STRIDE 144          // bytes per A smem row (128 data + 16 pad)
#define B_STRIDE 272          // bytes per B smem row (256 data + 16 pad)
#define SM_B_HI  0
#define SM_B_LO  69632        // 256*272
#define SM_A_HI(b) (139264 + (b) * 36864)
#define SM_A_LO(b) (157696 + (b) * 36864)
#define SM_TOTAL 212992

__device__ __forceinline__ void ldsm4(u32* r, u32 addr) {
    asm volatile("ldmatrix.sync.aligned.m8n8.x4.shared.b16 {%0,%1,%2,%3}, [%4];"
                 : "=r"(r[0]), "=r"(r[1]), "=r"(r[2]), "=r"(r[3]) : "r"(addr));
}
__device__ __forceinline__ void ldsm4t(u32* r, u32 addr) {
    asm volatile("ldmatrix.sync.aligned.m8n8.x4.trans.shared.b16 {%0,%1,%2,%3}, [%4];"
                 : "=r"(r[0]), "=r"(r[1]), "=r"(r[2]), "=r"(r[3]) : "r"(addr));
}
__device__ __forceinline__ void mma16816(float* d, const u32* a, u32 b0, u32 b1) {
    asm volatile("mma.sync.aligned.m16n8k16.row.col.f32.bf16.bf16.f32 "
                 "{%0,%1,%2,%3}, {%4,%5,%6,%7}, {%8,%9}, {%0,%1,%2,%3};"
                 : "+f"(d[0]), "+f"(d[1]), "+f"(d[2]), "+f"(d[3])
                 : "r"(a[0]), "r"(a[1]), "r"(a[2]), "r"(a[3]), "r"(b0), "r"(b1));
}
__device__ __forceinline__ void cp16(u32 dst, const void* src) {
    asm volatile("cp.async.cg.shared.global [%0], [%1], 16;" :: "r"(dst), "l"(src) : "memory");
}
#define CP_COMMIT() asm volatile("cp.async.commit_group;" ::: "memory")
#define CP_WAIT1()  asm volatile("cp.async.wait_group 1;" ::: "memory")

__global__ void __launch_bounds__(256, 1) gemm_mma_kernel(float* __restrict__ out)
{
    extern __shared__ char smem[];
    u32 sbase;
    asm("{ .reg .u64 t; cvta.to.shared.u64 t, %1; cvt.u32.u64 %0, t; }"
        : "=r"(sbase) : "l"(smem));

    const int tid    = threadIdx.x;
    const int wid    = tid >> 5;
    const int lane   = tid & 31;
    const int warp_m = wid & 1;
    const int warp_n = wid >> 1;

    const int t0 = blockIdx.x * 3;
    int ntiles = NTILES - t0; if (ntiles > 3) ntiles = 3;
    if (ntiles <= 0) return;
    const int total_chunks = ntiles * 4;

    // ---- prologue group 0: B (resident) + A chunk 0 ----
    for (int i = tid; i < 4096; i += 256) {          // B: 256 rows x 16 segs
        int r = i >> 4, sg = i & 15;
        u32 dst = sbase + (u32)(r * B_STRIDE + sg * 16);
        const char* srcH = (const char*)g_Bh + (size_t)r * 256 + sg * 16;
        const char* srcL = (const char*)g_Bl + (size_t)r * 256 + sg * 16;
        cp16(dst + SM_B_HI, srcH);
        cp16(dst + SM_B_LO, srcL);
    }
    for (int i = tid; i < 1024; i += 256) {          // A chunk 0 -> buf 0
        int r = i >> 3, sg = i & 7;
        u32 dsto = (u32)(r * A_STRIDE + sg * 16);
        size_t go = ((size_t)(t0 * 128 + r) * 256) * 2 + sg * 16;
        cp16(sbase + SM_A_HI(0) + dsto, (const char*)g_Ah + go);
        cp16(sbase + SM_A_LO(0) + dsto, (const char*)g_Al + go);
    }
    CP_COMMIT();
    // ---- prologue group 1: A chunk 1 -> buf 1 ----
    for (int i = tid; i < 1024; i += 256) {
        int r = i >> 3, sg = i & 7;
        u32 dsto = (u32)(r * A_STRIDE + sg * 16);
        size_t go = ((size_t)(t0 * 128 + r) * 256 + 64) * 2 + sg * 16;
        cp16(sbase + SM_A_HI(1) + dsto, (const char*)g_Ah + go);
        cp16(sbase + SM_A_LO(1) + dsto, (const char*)g_Al + go);
    }
    CP_COMMIT();

    float acc[4][4][4];
#pragma unroll
    for (int mi = 0; mi < 4; mi++)
#pragma unroll
        for (int ni = 0; ni < 4; ni++)
#pragma unroll
            for (int q = 0; q < 4; q++) acc[mi][ni][q] = 0.f;

    for (int cc = 0; cc < total_chunks; cc++) {
        const int buf = cc & 1;
        const int c   = cc & 3;          // chunk within tile
        CP_WAIT1();
        __syncthreads();

        // ---- mainloop on buf ----
#pragma unroll
        for (int k16 = 0; k16 < 4; k16++) {
            u32 bh[2][4], bl[2][4];
#pragma unroll
            for (int ng = 0; ng < 2; ng++) {
                u32 baddr = sbase + SM_B_HI
                          + (u32)((c * 64 + k16 * 16 + (lane & 15)) * B_STRIDE)
                          + (u32)((warp_n * 32 + ng * 16 + (lane >> 4) * 8) * 2);
                ldsm4t(bh[ng], baddr);
                ldsm4t(bl[ng], baddr + (SM_B_LO - SM_B_HI));
            }
#pragma unroll
            for (int mi = 0; mi < 4; mi++) {
                u32 aaddr = sbase + SM_A_HI(buf)
                          + (u32)((warp_m * 64 + mi * 16 + (lane & 15)) * A_STRIDE)
                          + (u32)(k16 * 32 + (lane >> 4) * 16);
                u32 ah[4], al[4];
                ldsm4(ah, aaddr);
                ldsm4(al, aaddr + (SM_A_LO(buf) - SM_A_HI(buf)));
#pragma unroll
                for (int ni = 0; ni < 4; ni++) {
                    int ng = ni >> 1;
                    int hf = (ni & 1) * 2;
                    mma16816(acc[mi][ni], ah, bh[ng][hf], bh[ng][hf + 1]);
                    mma16816(acc[mi][ni], al, bh[ng][hf], bh[ng][hf + 1]);
                    mma16816(acc[mi][ni], ah, bl[ng][hf], bl[ng][hf + 1]);
                }
            }
        }
        __syncthreads();   // everyone done reading buf before overwrite

        // ---- prefetch chunk cc+2 into this buf ----
        int nc = cc + 2;
        if (nc < total_chunks) {
            int ntile = t0 + (nc >> 2);
            int nch   = nc & 3;
            for (int i = tid; i < 1024; i += 256) {
                int r = i >> 3, sg = i & 7;
                u32 dsto = (u32)(r * A_STRIDE + sg * 16);
                size_t go = ((size_t)(ntile * 128 + r) * 256 + nch * 64) * 2 + sg * 16;
                cp16(sbase + SM_A_HI(buf) + dsto, (const char*)g_Ah + go);
                cp16(sbase + SM_A_LO(buf) + dsto, (const char*)g_Al + go);
            }
        }
        CP_COMMIT();       // always commit to keep per-thread group counts aligned

        // ---- tile epilogue (overlaps in-flight prefetch) ----
        if (c == 3) {
            int row0 = (t0 + (cc >> 2)) * 128;
#pragma unroll
            for (int mi = 0; mi < 4; mi++) {
                int r0 = row0 + warp_m * 64 + mi * 16 + (lane >> 2);
#pragma unroll
                for (int ni = 0; ni < 4; ni++) {
                    int col = warp_n * 32 + ni * 8 + (lane & 3) * 2;
                    if (r0 < N_NODES) {
                        float2 v;
                        v.x = fmaxf(acc[mi][ni][0], 0.f);
                        v.y = fmaxf(acc[mi][ni][1], 0.f);
                        *(float2*)(out + (size_t)r0 * DIM + col) = v;
                    }
                    if (r0 + 8 < N_NODES) {
                        float2 v;
                        v.x = fmaxf(acc[mi][ni][2], 0.f);
                        v.y = fmaxf(acc[mi][ni][3], 0.f);
                        *(float2*)(out + (size_t)(r0 + 8) * DIM + col) = v;
                    }
                    acc[mi][ni][0] = 0.f; acc[mi][ni][1] = 0.f;
                    acc[mi][ni][2] = 0.f; acc[mi][ni][3] = 0.f;
                }
            }
        }
    }
}

// ---------------------------------------------------------------------------
// Launcher
// ---------------------------------------------------------------------------
extern "C" void kernel_launch(void* const* d_in, const int* in_sizes, int n_in,
                              void* d_out, int out_size)
{
    (void)in_sizes; (void)n_in; (void)out_size;

    const float* h          = (const float*)d_in[0];
    const float* norm       = (const float*)d_in[1];
    const float* rel_emb    = (const float*)d_in[2];
    const float* W_neighbor = (const float*)d_in[3];
    const float* loop_w     = (const float*)d_in[4];
    const int*   edge_src   = (const int*)d_in[5];
    const int*   edge_dst   = (const int*)d_in[6];
    const int*   edge_type  = (const int*)d_in[7];
    float*       out        = (float*)d_out;

    prep_B_kernel<<<(256 * DIM + 255) / 256, 256>>>(W_neighbor, loop_w);
    {
        int n4 = N_NODES * DIM / 4;
        zero_S_kernel<<<(n4 + 255) / 256, 256>>>();
    }
    {
        long long total = (long long)N_EDGES * 32;
        scatter_edges_kernel<<<(int)((total + 255) / 256), 256>>>(h, rel_emb, edge_src, edge_dst, edge_type);
    }
    convert_A_kernel<<<(M_PAD * 32 + 255) / 256, 256>>>(h, norm);
    {
        static bool attr_set = false;
        if (!attr_set) {
            cudaFuncSetAttribute(gemm_mma_kernel,
                                 cudaFuncAttributeMaxDynamicSharedMemorySize, SM_TOTAL);
            attr_set = true;
        }
        gemm_mma_kernel<<<GRID_G, 256, SM_TOTAL>>>(out);
    }
}

// round 6
// speedup vs baseline: 1.6316x; 1.0085x over previous
#include <cuda_runtime.h>
#include <cuda_bf16.h>
#include <cstdint>

#define N_NODES 50000
#define N_EDGES 600000
#define DIM     128
#define M_PAD   50048
#define NTILES  391          // 50048 / 128

typedef unsigned int u32;
typedef unsigned short u16;

// ---------------------------------------------------------------------------
// Device scratch
// ---------------------------------------------------------------------------
__device__ float g_S[(size_t)N_NODES * DIM];                  // scatter accumulator
__device__ __align__(16) u16 g_Bh[256 * DIM];                 // B=[Wn;Wl] bf16 hi [K=256][N=128]
__device__ __align__(16) u16 g_Bl[256 * DIM];                 // bf16 lo
__device__ __align__(16) u16 g_Ah[(size_t)M_PAD * 256];       // A=[norm*S | h] bf16 hi [M][K=256]
__device__ __align__(16) u16 g_Al[(size_t)M_PAD * 256];       // bf16 lo

// ---------------------------------------------------------------------------
// Kernel 1: zero S + prep B in one launch
//   blocks [0, 6250)       : zero g_S (float4 per thread)
//   blocks [6250, 6250+128): B[k][n] bf16 hi/lo split
// ---------------------------------------------------------------------------
#define ZERO_BLOCKS 6250
__global__ void init_kernel(const float* __restrict__ W_neighbor,
                            const float* __restrict__ loop_weight)
{
    int b = blockIdx.x;
    if (b < ZERO_BLOCKS) {
        size_t i = (size_t)b * 256 + threadIdx.x;
        if (i < (size_t)N_NODES * DIM / 4)
            ((float4*)g_S)[i] = make_float4(0.f, 0.f, 0.f, 0.f);
    } else {
        int i = (b - ZERO_BLOCKS) * 256 + threadIdx.x;   // < 32768
        int k = i >> 7;
        int n = i & 127;
        float w = (k < 128) ? W_neighbor[(size_t)k * DIM + n]
                            : loop_weight[(size_t)(k - 128) * DIM + n];
        __nv_bfloat16 hi = __float2bfloat16_rn(w);
        __nv_bfloat16 lo = __float2bfloat16_rn(w - __bfloat162float(hi));
        g_Bh[i] = __bfloat16_as_ushort(hi);
        g_Bl[i] = __bfloat16_as_ushort(lo);
    }
}

// ---------------------------------------------------------------------------
// Kernel 2: edge scatter (one warp per edge) — proven R1 version
// ---------------------------------------------------------------------------
__global__ void __launch_bounds__(256) scatter_edges_kernel(
    const float* __restrict__ h,
    const float* __restrict__ rel_emb,
    const int*   __restrict__ edge_src,
    const int*   __restrict__ edge_dst,
    const int*   __restrict__ edge_type)
{
    int warp = (int)((blockIdx.x * (unsigned)blockDim.x + threadIdx.x) >> 5);
    int lane = threadIdx.x & 31;
    if (warp >= N_EDGES) return;

    int s = __ldg(edge_src  + warp);
    int d = __ldg(edge_dst  + warp);
    int t = __ldg(edge_type + warp);

    const float4 hv = *(const float4*)(h       + (size_t)s * DIM + lane * 4);
    const float4 rv = *(const float4*)(rel_emb + (size_t)t * DIM + lane * 4);

    float4 m = make_float4(hv.x + rv.x, hv.y + rv.y, hv.z + rv.z, hv.w + rv.w);
    float* outp = g_S + (size_t)d * DIM + lane * 4;
    asm volatile("red.global.add.v4.f32 [%0], {%1, %2, %3, %4};"
                 :: "l"(outp), "f"(m.x), "f"(m.y), "f"(m.z), "f"(m.w) : "memory");
}

// ---------------------------------------------------------------------------
// Kernel 3: convert A = [norm*S | h] to bf16 hi/lo (pads rows >= N_NODES)
// ---------------------------------------------------------------------------
__global__ void __launch_bounds__(256) convert_A_kernel(
    const float* __restrict__ h,
    const float* __restrict__ norm)
{
    int i = blockIdx.x * blockDim.x + threadIdx.x;
    if (i >= M_PAD * 32) return;
    int row = i >> 5;
    int seg = i & 31;

    float vals[8];
    if (row < N_NODES) {
        const float* src;
        float sc;
        if (seg < 16) { src = g_S + (size_t)row * DIM + seg * 8;        sc = __ldg(norm + row); }
        else          { src = h   + (size_t)row * DIM + (seg - 16) * 8; sc = 1.f; }
        float4 a = ((const float4*)src)[0];
        float4 b = ((const float4*)src)[1];
        vals[0] = a.x * sc; vals[1] = a.y * sc; vals[2] = a.z * sc; vals[3] = a.w * sc;
        vals[4] = b.x * sc; vals[5] = b.y * sc; vals[6] = b.z * sc; vals[7] = b.w * sc;
    } else {
#pragma unroll
        for (int j = 0; j < 8; j++) vals[j] = 0.f;
    }

    u32 hiw[4], low[4];
#pragma unroll
    for (int p = 0; p < 4; p++) {
        __nv_bfloat16 h0 = __float2bfloat16_rn(vals[2 * p]);
        __nv_bfloat16 h1 = __float2bfloat16_rn(vals[2 * p + 1]);
        __nv_bfloat16 l0 = __float2bfloat16_rn(vals[2 * p]     - __bfloat162float(h0));
        __nv_bfloat16 l1 = __float2bfloat16_rn(vals[2 * p + 1] - __bfloat162float(h1));
        hiw[p] = (u32)__bfloat16_as_ushort(h0) | ((u32)__bfloat16_as_ushort(h1) << 16);
        low[p] = (u32)__bfloat16_as_ushort(l0) | ((u32)__bfloat16_as_ushort(l1) << 16);
    }
    size_t v4 = (size_t)row * 32 + seg;
    ((uint4*)g_Ah)[v4] = make_uint4(hiw[0], hiw[1], hiw[2], hiw[3]);
    ((uint4*)g_Al)[v4] = make_uint4(low[0], low[1], low[2], low[3]);
}

// ---------------------------------------------------------------------------
// Kernel 4: multistage tensor-core GEMM.
//   out = relu( A @ B ),  128x128 CTA tile, 4 warps (64x64 warp tiles),
//   3-stage cp.async ring staging A and B 64-K chunks, 1 sync per chunk.
// ---------------------------------------------------------------------------
#define A_STRIDE 144          // bytes per A smem row (128B data + 16 pad)
#define B_STRIDE 272          // bytes per B smem row (256B data + 16 pad)
#define STG_A_HI 0
#define STG_A_LO 18432        // 128*144
#define STG_B_HI 36864
#define STG_B_LO 54272        // 36864 + 64*272
#define STG_SIZE 71680
#define SM_TOTAL (3 * STG_SIZE)   // 215040

__device__ __forceinline__ void ldsm4(u32* r, u32 addr) {
    asm volatile("ldmatrix.sync.aligned.m8n8.x4.shared.b16 {%0,%1,%2,%3}, [%4];"
                 : "=r"(r[0]), "=r"(r[1]), "=r"(r[2]), "=r"(r[3]) : "r"(addr));
}
__device__ __forceinline__ void ldsm4t(u32* r, u32 addr) {
    asm volatile("ldmatrix.sync.aligned.m8n8.x4.trans.shared.b16 {%0,%1,%2,%3}, [%4];"
                 : "=r"(r[0]), "=r"(r[1]), "=r"(r[2]), "=r"(r[3]) : "r"(addr));
}
__device__ __forceinline__ void mma16816(float* d, const u32* a, u32 b0, u32 b1) {
    asm volatile("mma.sync.aligned.m16n8k16.row.col.f32.bf16.bf16.f32 "
                 "{%0,%1,%2,%3}, {%4,%5,%6,%7}, {%8,%9}, {%0,%1,%2,%3};"
                 : "+f"(d[0]), "+f"(d[1]), "+f"(d[2]), "+f"(d[3])
                 : "r"(a[0]), "r"(a[1]), "r"(a[2]), "r"(a[3]), "r"(b0), "r"(b1));
}
__device__ __forceinline__ void cp16(u32 dst, const void* src) {
    asm volatile("cp.async.cg.shared.global [%0], [%1], 16;" :: "r"(dst), "l"(src) : "memory");
}
#define CP_COMMIT() asm volatile("cp.async.commit_group;" ::: "memory")
#define CP_WAIT1()  asm volatile("cp.async.wait_group 1;" ::: "memory")

// issue loads for chunk c of tile row0 into stage s
__device__ __forceinline__ void issue_chunk(u32 sbase, int tid, int row0, int c, int s)
{
    u32 stage = sbase + (u32)(s * STG_SIZE);
    // A: 128 rows x 64 K: 8 segs of 16B per row (hi and lo)
    for (int i = tid; i < 1024; i += 128) {
        int r = i >> 3, sg = i & 7;
        u32 dsto = (u32)(r * A_STRIDE + sg * 16);
        size_t go = ((size_t)(row0 + r) * 256 + c * 64) * 2 + sg * 16;
        cp16(stage + STG_A_HI + dsto, (const char*)g_Ah + go);
        cp16(stage + STG_A_LO + dsto, (const char*)g_Al + go);
    }
    // B: 64 rows x 128 N: 16 segs of 16B per row
    for (int i = tid; i < 1024; i += 128) {
        int r = i >> 4, sg = i & 15;
        u32 dsto = (u32)(r * B_STRIDE + sg * 16);
        size_t go = ((size_t)(c * 64 + r) * 128) * 2 + sg * 16;
        cp16(stage + STG_B_HI + dsto, (const char*)g_Bh + go);
        cp16(stage + STG_B_LO + dsto, (const char*)g_Bl + go);
    }
}

__global__ void __launch_bounds__(128, 1) gemm_mma_kernel(float* __restrict__ out)
{
    extern __shared__ char smem[];
    u32 sbase;
    asm("{ .reg .u64 t; cvta.to.shared.u64 t, %1; cvt.u32.u64 %0, t; }"
        : "=r"(sbase) : "l"(smem));

    const int tid    = threadIdx.x;
    const int wid    = tid >> 5;
    const int lane   = tid & 31;
    const int warp_m = wid & 1;          // 0,1 -> 64-row halves
    const int warp_n = wid >> 1;         // 0,1 -> 64-col halves
    const int row0   = blockIdx.x * 128;

    // prologue: issue chunks 0 and 1
    issue_chunk(sbase, tid, row0, 0, 0);
    CP_COMMIT();
    issue_chunk(sbase, tid, row0, 1, 1);
    CP_COMMIT();

    float acc[4][8][4];
#pragma unroll
    for (int mi = 0; mi < 4; mi++)
#pragma unroll
        for (int ni = 0; ni < 8; ni++)
#pragma unroll
            for (int q = 0; q < 4; q++) acc[mi][ni][q] = 0.f;

#pragma unroll
    for (int c = 0; c < 4; c++) {
        CP_WAIT1();
        __syncthreads();

        // issue chunk c+2 into stage (c+2)%3 (freed at iteration c-1)
        if (c < 2) issue_chunk(sbase, tid, row0, c + 2, (c + 2) % 3);
        CP_COMMIT();

        const u32 stage = sbase + (u32)((c % 3) * STG_SIZE);
#pragma unroll
        for (int k16 = 0; k16 < 4; k16++) {
            u32 bh[4][4], bl[4][4];
#pragma unroll
            for (int ng = 0; ng < 4; ng++) {
                u32 baddr = stage + STG_B_HI
                          + (u32)((k16 * 16 + (lane & 15)) * B_STRIDE)
                          + (u32)((warp_n * 64 + ng * 16 + (lane >> 4) * 8) * 2);
                ldsm4t(bh[ng], baddr);
                ldsm4t(bl[ng], baddr + (STG_B_LO - STG_B_HI));
            }
#pragma unroll
            for (int mi = 0; mi < 4; mi++) {
                u32 aaddr = stage + STG_A_HI
                          + (u32)((warp_m * 64 + mi * 16 + (lane & 15)) * A_STRIDE)
                          + (u32)(k16 * 32 + (lane >> 4) * 16);
                u32 ah[4], al[4];
                ldsm4(ah, aaddr);
                ldsm4(al, aaddr + (STG_A_LO - STG_A_HI));
#pragma unroll
                for (int ni = 0; ni < 8; ni++) {
                    int ng = ni >> 1;
                    int hf = (ni & 1) * 2;
                    mma16816(acc[mi][ni], ah, bh[ng][hf], bh[ng][hf + 1]);
                    mma16816(acc[mi][ni], al, bh[ng][hf], bh[ng][hf + 1]);
                    mma16816(acc[mi][ni], ah, bl[ng][hf], bl[ng][hf + 1]);
                }
            }
        }
        __syncthreads();   // all warps done with this stage before it is refilled
    }

    // epilogue: relu + store (64x64 per warp)
#pragma unroll
    for (int mi = 0; mi < 4; mi++) {
        int r0 = row0 + warp_m * 64 + mi * 16 + (lane >> 2);
#pragma unroll
        for (int ni = 0; ni < 8; ni++) {
            int col = warp_n * 64 + ni * 8 + (lane & 3) * 2;
            if (r0 < N_NODES) {
                float2 v;
                v.x = fmaxf(acc[mi][ni][0], 0.f);
                v.y = fmaxf(acc[mi][ni][1], 0.f);
                *(float2*)(out + (size_t)r0 * DIM + col) = v;
            }
            if (r0 + 8 < N_NODES) {
                float2 v;
                v.x = fmaxf(acc[mi][ni][2], 0.f);
                v.y = fmaxf(acc[mi][ni][3], 0.f);
                *(float2*)(out + (size_t)(r0 + 8) * DIM + col) = v;
            }
        }
    }
}

// ---------------------------------------------------------------------------
// Launcher
// ---------------------------------------------------------------------------
extern "C" void kernel_launch(void* const* d_in, const int* in_sizes, int n_in,
                              void* d_out, int out_size)
{
    (void)in_sizes; (void)n_in; (void)out_size;

    const float* h          = (const float*)d_in[0];
    const float* norm       = (const float*)d_in[1];
    const float* rel_emb    = (const float*)d_in[2];
    const float* W_neighbor = (const float*)d_in[3];
    const float* loop_w     = (const float*)d_in[4];
    const int*   edge_src   = (const int*)d_in[5];
    const int*   edge_dst   = (const int*)d_in[6];
    const int*   edge_type  = (const int*)d_in[7];
    float*       out        = (float*)d_out;

    init_kernel<<<ZERO_BLOCKS + 128, 256>>>(W_neighbor, loop_w);
    {
        long long total = (long long)N_EDGES * 32;
        scatter_edges_kernel<<<(int)((total + 255) / 256), 256>>>(h, rel_emb, edge_src, edge_dst, edge_type);
    }
    convert_A_kernel<<<(M_PAD * 32 + 255) / 256, 256>>>(h, norm);
    {
        static bool attr_set = false;
        if (!attr_set) {
            cudaFuncSetAttribute(gemm_mma_kernel,
                                 cudaFuncAttributeMaxDynamicSharedMemorySize, SM_TOTAL);
            attr_set = true;
        }
        gemm_mma_kernel<<<NTILES, 128, SM_TOTAL>>>(out);
    }
}

// round 7
// speedup vs baseline: 1.7220x; 1.0554x over previous
#include <cuda_runtime.h>
#include <cuda_bf16.h>
#include <cstdint>

#define N_NODES 50000
#define N_EDGES 600000
#define DIM     128
#define NTILES  391          // ceil(50000/128)

typedef unsigned int u32;
typedef unsigned short u16;

// ---------------------------------------------------------------------------
// Device scratch
// ---------------------------------------------------------------------------
__device__ float g_S[(size_t)N_NODES * DIM];                  // scatter accumulator
__device__ __align__(16) u16 g_Bh[256 * DIM];                 // B=[Wn;Wl] bf16 hi [K=256][N=128]
__device__ __align__(16) u16 g_Bl[256 * DIM];                 // bf16 lo

// ---------------------------------------------------------------------------
// Kernel 1: zero S + prep B in one launch
// ---------------------------------------------------------------------------
#define ZERO_BLOCKS 6250
__global__ void init_kernel(const float* __restrict__ W_neighbor,
                            const float* __restrict__ loop_weight)
{
    int b = blockIdx.x;
    if (b < ZERO_BLOCKS) {
        size_t i = (size_t)b * 256 + threadIdx.x;
        if (i < (size_t)N_NODES * DIM / 4)
            ((float4*)g_S)[i] = make_float4(0.f, 0.f, 0.f, 0.f);
    } else {
        int i = (b - ZERO_BLOCKS) * 256 + threadIdx.x;   // < 32768
        int k = i >> 7;
        int n = i & 127;
        float w = (k < 128) ? W_neighbor[(size_t)k * DIM + n]
                            : loop_weight[(size_t)(k - 128) * DIM + n];
        __nv_bfloat16 hi = __float2bfloat16_rn(w);
        __nv_bfloat16 lo = __float2bfloat16_rn(w - __bfloat162float(hi));
        g_Bh[i] = __bfloat16_as_ushort(hi);
        g_Bl[i] = __bfloat16_as_ushort(lo);
    }
}

// ---------------------------------------------------------------------------
// Kernel 2: edge scatter (one warp per edge) — proven R1 version
// ---------------------------------------------------------------------------
__global__ void __launch_bounds__(256) scatter_edges_kernel(
    const float* __restrict__ h,
    const float* __restrict__ rel_emb,
    const int*   __restrict__ edge_src,
    const int*   __restrict__ edge_dst,
    const int*   __restrict__ edge_type)
{
    int warp = (int)((blockIdx.x * (unsigned)blockDim.x + threadIdx.x) >> 5);
    int lane = threadIdx.x & 31;
    if (warp >= N_EDGES) return;

    int s = __ldg(edge_src  + warp);
    int d = __ldg(edge_dst  + warp);
    int t = __ldg(edge_type + warp);

    const float4 hv = *(const float4*)(h       + (size_t)s * DIM + lane * 4);
    const float4 rv = *(const float4*)(rel_emb + (size_t)t * DIM + lane * 4);

    float4 m = make_float4(hv.x + rv.x, hv.y + rv.y, hv.z + rv.z, hv.w + rv.w);
    float* outp = g_S + (size_t)d * DIM + lane * 4;
    asm volatile("red.global.add.v4.f32 [%0], {%1, %2, %3, %4};"
                 :: "l"(outp), "f"(m.x), "f"(m.y), "f"(m.z), "f"(m.w) : "memory");
}

// ---------------------------------------------------------------------------
// Kernel 3: fused GEMM with in-kernel A conversion.
//   out = relu( [norm*S | h] @ [Wn; Wl] )
// CTA: 256 threads (8 warps), tile 128(M) x 128(N), K=256 in 4 chunks of 64.
// Warp tile 32x64.  A staged by LDG+CVT+STS (fp32 -> bf16 hi/lo), B via
// cp.async from pre-split g_Bh/g_Bl.  Double-buffered smem.
// ---------------------------------------------------------------------------
#define A_STRIDE 144          // bytes per A smem row (128B data + 16 pad)
#define B_STRIDE 272          // bytes per B smem row (256B data + 16 pad)
#define AB_SIZE  18432        // 128*144
#define BB_SIZE  17408        // 64*272
// layout: A_HI0 A_LO0 A_HI1 A_LO1 B_HI0 B_LO0 B_HI1 B_LO1
#define OFF_A_HI(s) ((s) * 36864)
#define OFF_A_LO(s) ((s) * 36864 + 18432)
#define OFF_B_HI(s) (73728 + (s) * 34816)
#define OFF_B_LO(s) (73728 + (s) * 34816 + 17408)
#define SM_TOTAL 143360

__device__ __forceinline__ void ldsm4(u32* r, u32 addr) {
    asm volatile("ldmatrix.sync.aligned.m8n8.x4.shared.b16 {%0,%1,%2,%3}, [%4];"
                 : "=r"(r[0]), "=r"(r[1]), "=r"(r[2]), "=r"(r[3]) : "r"(addr));
}
__device__ __forceinline__ void ldsm4t(u32* r, u32 addr) {
    asm volatile("ldmatrix.sync.aligned.m8n8.x4.trans.shared.b16 {%0,%1,%2,%3}, [%4];"
                 : "=r"(r[0]), "=r"(r[1]), "=r"(r[2]), "=r"(r[3]) : "r"(addr));
}
__device__ __forceinline__ void mma16816(float* d, const u32* a, u32 b0, u32 b1) {
    asm volatile("mma.sync.aligned.m16n8k16.row.col.f32.bf16.bf16.f32 "
                 "{%0,%1,%2,%3}, {%4,%5,%6,%7}, {%8,%9}, {%0,%1,%2,%3};"
                 : "+f"(d[0]), "+f"(d[1]), "+f"(d[2]), "+f"(d[3])
                 : "r"(a[0]), "r"(a[1]), "r"(a[2]), "r"(a[3]), "r"(b0), "r"(b1));
}
__device__ __forceinline__ void cp16(u32 dst, const void* src) {
    asm volatile("cp.async.cg.shared.global [%0], [%1], 16;" :: "r"(dst), "l"(src) : "memory");
}
#define CP_COMMIT() asm volatile("cp.async.commit_group;" ::: "memory")

// stage A chunk c of this tile into smem buffers at a_hi/a_lo.
// 256 threads, 128 rows: 2 threads per row, 32 cols each.
__device__ __forceinline__ void stage_A(const float* __restrict__ h,
                                        const float* __restrict__ norm,
                                        int row0, int c, int tid,
                                        char* smem, u32 a_hi_off)
{
    int row  = tid >> 1;
    int half = tid & 1;
    int gr   = row0 + row;
    const float* src;
    float sc;
    bool valid = (gr < N_NODES);
    if (c < 2) {
        src = g_S + (size_t)gr * DIM + c * 64 + half * 32;
        sc  = valid ? __ldg(norm + gr) : 0.f;
    } else {
        src = h + (size_t)gr * DIM + (c - 2) * 64 + half * 32;
        sc  = 1.f;
    }
#pragma unroll
    for (int j8 = 0; j8 < 4; j8++) {
        float vals[8];
        if (valid) {
            float4 a = ((const float4*)src)[j8 * 2];
            float4 b = ((const float4*)src)[j8 * 2 + 1];
            vals[0] = a.x * sc; vals[1] = a.y * sc; vals[2] = a.z * sc; vals[3] = a.w * sc;
            vals[4] = b.x * sc; vals[5] = b.y * sc; vals[6] = b.z * sc; vals[7] = b.w * sc;
        } else {
#pragma unroll
            for (int q = 0; q < 8; q++) vals[q] = 0.f;
        }
        u32 hiw[4], low[4];
#pragma unroll
        for (int p = 0; p < 4; p++) {
            __nv_bfloat16 h0 = __float2bfloat16_rn(vals[2 * p]);
            __nv_bfloat16 h1 = __float2bfloat16_rn(vals[2 * p + 1]);
            __nv_bfloat16 l0 = __float2bfloat16_rn(vals[2 * p]     - __bfloat162float(h0));
            __nv_bfloat16 l1 = __float2bfloat16_rn(vals[2 * p + 1] - __bfloat162float(h1));
            hiw[p] = (u32)__bfloat16_as_ushort(h0) | ((u32)__bfloat16_as_ushort(h1) << 16);
            low[p] = (u32)__bfloat16_as_ushort(l0) | ((u32)__bfloat16_as_ushort(l1) << 16);
        }
        u32 off = (u32)(row * A_STRIDE + (half * 32 + j8 * 8) * 2);
        *(uint4*)(smem + a_hi_off + off)         = make_uint4(hiw[0], hiw[1], hiw[2], hiw[3]);
        *(uint4*)(smem + a_hi_off + 18432 + off) = make_uint4(low[0], low[1], low[2], low[3]);
    }
}

// issue cp.async for B chunk c into stage buffer s
__device__ __forceinline__ void issue_B(u32 sbase, int tid, int c, int s)
{
    u32 bh = sbase + OFF_B_HI(s);
    u32 bl = sbase + OFF_B_LO(s);
#pragma unroll
    for (int it = 0; it < 4; it++) {
        int i  = tid + it * 256;           // < 1024
        int r  = i >> 4;
        int sg = i & 15;
        u32 dsto = (u32)(r * B_STRIDE + sg * 16);
        size_t go = (size_t)(c * 64 + r) * 256 + sg * 16;
        cp16(bh + dsto, (const char*)g_Bh + go);
        cp16(bl + dsto, (const char*)g_Bl + go);
    }
}

__global__ void __launch_bounds__(256, 1) gemm_fused_kernel(
    const float* __restrict__ h,
    const float* __restrict__ norm,
    float* __restrict__ out)
{
    extern __shared__ char smem[];
    u32 sbase;
    asm("{ .reg .u64 t; cvta.to.shared.u64 t, %1; cvt.u32.u64 %0, t; }"
        : "=r"(sbase) : "l"(smem));

    const int tid    = threadIdx.x;
    const int wid    = tid >> 5;
    const int lane   = tid & 31;
    const int warp_m = wid & 3;          // 4 x 32-row strips
    const int warp_n = wid >> 2;         // 2 x 64-col halves
    const int row0   = blockIdx.x * 128;

    // prologue: B0, B1 async; A0 synchronous
    issue_B(sbase, tid, 0, 0);
    CP_COMMIT();
    issue_B(sbase, tid, 1, 1);
    CP_COMMIT();
    stage_A(h, norm, row0, 0, tid, smem, OFF_A_HI(0));

    float acc[2][8][4];
#pragma unroll
    for (int mi = 0; mi < 2; mi++)
#pragma unroll
        for (int ni = 0; ni < 8; ni++)
#pragma unroll
            for (int q = 0; q < 4; q++) acc[mi][ni][q] = 0.f;

#pragma unroll
    for (int c = 0; c < 4; c++) {
        const int s = c & 1;
        // wait for B[c]; keep at most 1 younger group in flight
        if (c < 2) asm volatile("cp.async.wait_group 1;" ::: "memory");
        else       asm volatile("cp.async.wait_group 0;" ::: "memory");
        __syncthreads();

        const u32 a_hi = sbase + OFF_A_HI(s);
        const u32 b_hi = sbase + OFF_B_HI(s);
#pragma unroll
        for (int k16 = 0; k16 < 4; k16++) {
            u32 bh[4][4], bl[4][4];
#pragma unroll
            for (int ng = 0; ng < 4; ng++) {
                u32 baddr = b_hi
                          + (u32)((k16 * 16 + (lane & 15)) * B_STRIDE)
                          + (u32)((warp_n * 64 + ng * 16 + (lane >> 4) * 8) * 2);
                ldsm4t(bh[ng], baddr);
                ldsm4t(bl[ng], baddr + BB_SIZE);
            }
#pragma unroll
            for (int mi = 0; mi < 2; mi++) {
                u32 aaddr = a_hi
                          + (u32)((warp_m * 32 + mi * 16 + (lane & 15)) * A_STRIDE)
                          + (u32)(k16 * 32 + (lane >> 4) * 16);
                u32 ah[4], al[4];
                ldsm4(ah, aaddr);
                ldsm4(al, aaddr + AB_SIZE);
#pragma unroll
                for (int ni = 0; ni < 8; ni++) {
                    int ng = ni >> 1;
                    int hf = (ni & 1) * 2;
                    mma16816(acc[mi][ni], ah, bh[ng][hf], bh[ng][hf + 1]);
                    mma16816(acc[mi][ni], al, bh[ng][hf], bh[ng][hf + 1]);
                    mma16816(acc[mi][ni], ah, bl[ng][hf], bl[ng][hf + 1]);
                }
            }
        }

        // stage A[c+1] into the other buffer (overlaps other warps' MMA)
        if (c < 3) stage_A(h, norm, row0, c + 1, tid, smem, OFF_A_HI(s ^ 1));
        __syncthreads();
        // refill B buffer s with chunk c+2 (safe: all warps done reading it)
        if (c < 2) { issue_B(sbase, tid, c + 2, s); CP_COMMIT(); }
    }

    // epilogue: relu + store (32x64 per warp)
#pragma unroll
    for (int mi = 0; mi < 2; mi++) {
        int r0 = row0 + warp_m * 32 + mi * 16 + (lane >> 2);
#pragma unroll
        for (int ni = 0; ni < 8; ni++) {
            int col = warp_n * 64 + ni * 8 + (lane & 3) * 2;
            if (r0 < N_NODES) {
                float2 v;
                v.x = fmaxf(acc[mi][ni][0], 0.f);
                v.y = fmaxf(acc[mi][ni][1], 0.f);
                *(float2*)(out + (size_t)r0 * DIM + col) = v;
            }
            if (r0 + 8 < N_NODES) {
                float2 v;
                v.x = fmaxf(acc[mi][ni][2], 0.f);
                v.y = fmaxf(acc[mi][ni][3], 0.f);
                *(float2*)(out + (size_t)(r0 + 8) * DIM + col) = v;
            }
        }
    }
}

// ---------------------------------------------------------------------------
// Launcher
// ---------------------------------------------------------------------------
extern "C" void kernel_launch(void* const* d_in, const int* in_sizes, int n_in,
                              void* d_out, int out_size)
{
    (void)in_sizes; (void)n_in; (void)out_size;

    const float* h          = (const float*)d_in[0];
    const float* norm       = (const float*)d_in[1];
    const float* rel_emb    = (const float*)d_in[2];
    const float* W_neighbor = (const float*)d_in[3];
    const float* loop_w     = (const float*)d_in[4];
    const int*   edge_src   = (const int*)d_in[5];
    const int*   edge_dst   = (const int*)d_in[6];
    const int*   edge_type  = (const int*)d_in[7];
    float*       out        = (float*)d_out;

    init_kernel<<<ZERO_BLOCKS + 128, 256>>>(W_neighbor, loop_w);
    {
        long long total = (long long)N_EDGES * 32;
        scatter_edges_kernel<<<(int)((total + 255) / 256), 256>>>(h, rel_emb, edge_src, edge_dst, edge_type);
    }
    {
        static bool attr_set = false;
        if (!attr_set) {
            cudaFuncSetAttribute(gemm_fused_kernel,
                                 cudaFuncAttributeMaxDynamicSharedMemorySize, SM_TOTAL);
            attr_set = true;
        }
        gemm_fused_kernel<<<NTILES, 256, SM_TOTAL>>>(h, norm, out);
    }
}

// round 8
// speedup vs baseline: 1.8667x; 1.0841x over previous
#include <cuda_runtime.h>
#include <cuda_fp16.h>
#include <cstdint>

#define N_NODES 50000
#define N_EDGES 600000
#define DIM     128
#define NTILES  391          // ceil(50000/128)

typedef unsigned int u32;
typedef unsigned short u16;

// ---------------------------------------------------------------------------
// Device scratch
// ---------------------------------------------------------------------------
__device__ float g_S[(size_t)N_NODES * DIM];                  // scatter accumulator
__device__ __align__(16) u16 g_B[256 * DIM];                  // B=[Wn;Wl] fp16 [K=256][N=128]

// ---------------------------------------------------------------------------
// Kernel 1: zero S + prep B in one launch
// ---------------------------------------------------------------------------
#define ZERO_BLOCKS 6250
__global__ void init_kernel(const float* __restrict__ W_neighbor,
                            const float* __restrict__ loop_weight)
{
    int b = blockIdx.x;
    if (b < ZERO_BLOCKS) {
        size_t i = (size_t)b * 256 + threadIdx.x;
        if (i < (size_t)N_NODES * DIM / 4)
            ((float4*)g_S)[i] = make_float4(0.f, 0.f, 0.f, 0.f);
    } else {
        int i = (b - ZERO_BLOCKS) * 256 + threadIdx.x;   // < 32768
        int k = i >> 7;
        int n = i & 127;
        float w = (k < 128) ? W_neighbor[(size_t)k * DIM + n]
                            : loop_weight[(size_t)(k - 128) * DIM + n];
        g_B[i] = __half_as_ushort(__float2half_rn(w));
    }
}

// ---------------------------------------------------------------------------
// Kernel 2: edge scatter (one warp per edge) — proven R1 version
// ---------------------------------------------------------------------------
__global__ void __launch_bounds__(256) scatter_edges_kernel(
    const float* __restrict__ h,
    const float* __restrict__ rel_emb,
    const int*   __restrict__ edge_src,
    const int*   __restrict__ edge_dst,
    const int*   __restrict__ edge_type)
{
    int warp = (int)((blockIdx.x * (unsigned)blockDim.x + threadIdx.x) >> 5);
    int lane = threadIdx.x & 31;
    if (warp >= N_EDGES) return;

    int s = __ldg(edge_src  + warp);
    int d = __ldg(edge_dst  + warp);
    int t = __ldg(edge_type + warp);

    const float4 hv = *(const float4*)(h       + (size_t)s * DIM + lane * 4);
    const float4 rv = *(const float4*)(rel_emb + (size_t)t * DIM + lane * 4);

    float4 m = make_float4(hv.x + rv.x, hv.y + rv.y, hv.z + rv.z, hv.w + rv.w);
    float* outp = g_S + (size_t)d * DIM + lane * 4;
    asm volatile("red.global.add.v4.f32 [%0], {%1, %2, %3, %4};"
                 :: "l"(outp), "f"(m.x), "f"(m.y), "f"(m.z), "f"(m.w) : "memory");
}

// ---------------------------------------------------------------------------
// Kernel 3: fused GEMM, fp16 single product.
//   out = relu( [norm*S | h] @ [Wn; Wl] )
// CTA: 256 threads (8 warps), tile 128(M) x 128(N), K=256 in 4 chunks of 64.
// Warp tile 32x64.  A staged LDG+CVT+STS (fp32->fp16), B via cp.async.
// Double-buffered; 2 CTAs/SM.
// ---------------------------------------------------------------------------
#define A_STRIDE 144          // bytes per A smem row (128B data + 16 pad)
#define B_STRIDE 272          // bytes per B smem row (256B data + 16 pad)
#define OFF_A(s) ((s) * 18432)
#define OFF_B(s) (36864 + (s) * 17408)
#define SM_TOTAL 71680

__device__ __forceinline__ void ldsm4(u32* r, u32 addr) {
    asm volatile("ldmatrix.sync.aligned.m8n8.x4.shared.b16 {%0,%1,%2,%3}, [%4];"
                 : "=r"(r[0]), "=r"(r[1]), "=r"(r[2]), "=r"(r[3]) : "r"(addr));
}
__device__ __forceinline__ void ldsm4t(u32* r, u32 addr) {
    asm volatile("ldmatrix.sync.aligned.m8n8.x4.trans.shared.b16 {%0,%1,%2,%3}, [%4];"
                 : "=r"(r[0]), "=r"(r[1]), "=r"(r[2]), "=r"(r[3]) : "r"(addr));
}
__device__ __forceinline__ void mma16816(float* d, const u32* a, u32 b0, u32 b1) {
    asm volatile("mma.sync.aligned.m16n8k16.row.col.f32.f16.f16.f32 "
                 "{%0,%1,%2,%3}, {%4,%5,%6,%7}, {%8,%9}, {%0,%1,%2,%3};"
                 : "+f"(d[0]), "+f"(d[1]), "+f"(d[2]), "+f"(d[3])
                 : "r"(a[0]), "r"(a[1]), "r"(a[2]), "r"(a[3]), "r"(b0), "r"(b1));
}
__device__ __forceinline__ void cp16(u32 dst, const void* src) {
    asm volatile("cp.async.cg.shared.global [%0], [%1], 16;" :: "r"(dst), "l"(src) : "memory");
}
#define CP_COMMIT() asm volatile("cp.async.commit_group;" ::: "memory")

__device__ __forceinline__ u32 pack_h2(float lo, float hi) {
    u32 r;
    asm("cvt.rn.f16x2.f32 %0, %1, %2;" : "=r"(r) : "f"(hi), "f"(lo));
    return r;
}

// stage A chunk c into smem buffer a_off: 256 threads, 2 per row, 32 cols each
__device__ __forceinline__ void stage_A(const float* __restrict__ h,
                                        const float* __restrict__ norm,
                                        int row0, int c, int tid,
                                        char* smem, u32 a_off)
{
    int row  = tid >> 1;
    int half = tid & 1;
    int gr   = row0 + row;
    const float* src;
    float sc;
    bool valid = (gr < N_NODES);
    if (c < 2) {
        src = g_S + (size_t)gr * DIM + c * 64 + half * 32;
        sc  = valid ? __ldg(norm + gr) : 0.f;
    } else {
        src = h + (size_t)gr * DIM + (c - 2) * 64 + half * 32;
        sc  = 1.f;
    }
#pragma unroll
    for (int j8 = 0; j8 < 2; j8++) {      // two groups of 16 floats
        float vals[16];
        if (valid) {
#pragma unroll
            for (int q = 0; q < 4; q++) {
                float4 v = ((const float4*)src)[j8 * 4 + q];
                vals[q * 4 + 0] = v.x * sc; vals[q * 4 + 1] = v.y * sc;
                vals[q * 4 + 2] = v.z * sc; vals[q * 4 + 3] = v.w * sc;
            }
        } else {
#pragma unroll
            for (int q = 0; q < 16; q++) vals[q] = 0.f;
        }
        u32 w[8];
#pragma unroll
        for (int p = 0; p < 8; p++) w[p] = pack_h2(vals[2 * p], vals[2 * p + 1]);
        u32 off = (u32)(row * A_STRIDE + (half * 32 + j8 * 16) * 2);
        *(uint4*)(smem + a_off + off)      = make_uint4(w[0], w[1], w[2], w[3]);
        *(uint4*)(smem + a_off + off + 16) = make_uint4(w[4], w[5], w[6], w[7]);
    }
}

// issue cp.async for B chunk c into stage buffer s
__device__ __forceinline__ void issue_B(u32 sbase, int tid, int c, int s)
{
    u32 bb = sbase + OFF_B(s);
#pragma unroll
    for (int it = 0; it < 4; it++) {
        int i  = tid + it * 256;           // < 1024
        int r  = i >> 4;
        int sg = i & 15;
        u32 dsto = (u32)(r * B_STRIDE + sg * 16);
        size_t go = (size_t)(c * 64 + r) * 256 + sg * 16;
        cp16(bb + dsto, (const char*)g_B + go);
    }
}

__global__ void __launch_bounds__(256, 2) gemm_fused_kernel(
    const float* __restrict__ h,
    const float* __restrict__ norm,
    float* __restrict__ out)
{
    extern __shared__ char smem[];
    u32 sbase;
    asm("{ .reg .u64 t; cvta.to.shared.u64 t, %1; cvt.u32.u64 %0, t; }"
        : "=r"(sbase) : "l"(smem));

    const int tid    = threadIdx.x;
    const int wid    = tid >> 5;
    const int lane   = tid & 31;
    const int warp_m = wid & 3;          // 4 x 32-row strips
    const int warp_n = wid >> 2;         // 2 x 64-col halves
    const int row0   = blockIdx.x * 128;

    // prologue
    issue_B(sbase, tid, 0, 0);
    CP_COMMIT();
    issue_B(sbase, tid, 1, 1);
    CP_COMMIT();
    stage_A(h, norm, row0, 0, tid, smem, OFF_A(0));

    float acc[2][8][4];
#pragma unroll
    for (int mi = 0; mi < 2; mi++)
#pragma unroll
        for (int ni = 0; ni < 8; ni++)
#pragma unroll
            for (int q = 0; q < 4; q++) acc[mi][ni][q] = 0.f;

#pragma unroll
    for (int c = 0; c < 4; c++) {
        const int s = c & 1;
        if (c < 2) asm volatile("cp.async.wait_group 1;" ::: "memory");
        else       asm volatile("cp.async.wait_group 0;" ::: "memory");
        __syncthreads();

        const u32 a_sm = sbase + OFF_A(s);
        const u32 b_sm = sbase + OFF_B(s);
#pragma unroll
        for (int k16 = 0; k16 < 4; k16++) {
            u32 bh[4][4];
#pragma unroll
            for (int ng = 0; ng < 4; ng++) {
                u32 baddr = b_sm
                          + (u32)((k16 * 16 + (lane & 15)) * B_STRIDE)
                          + (u32)((warp_n * 64 + ng * 16 + (lane >> 4) * 8) * 2);
                ldsm4t(bh[ng], baddr);
            }
#pragma unroll
            for (int mi = 0; mi < 2; mi++) {
                u32 aaddr = a_sm
                          + (u32)((warp_m * 32 + mi * 16 + (lane & 15)) * A_STRIDE)
                          + (u32)(k16 * 32 + (lane >> 4) * 16);
                u32 ah[4];
                ldsm4(ah, aaddr);
#pragma unroll
                for (int ni = 0; ni < 8; ni++) {
                    int ng = ni >> 1;
                    int hf = (ni & 1) * 2;
                    mma16816(acc[mi][ni], ah, bh[ng][hf], bh[ng][hf + 1]);
                }
            }
        }

        // stage A[c+1] into the other buffer
        if (c < 3) stage_A(h, norm, row0, c + 1, tid, smem, OFF_A(s ^ 1));
        __syncthreads();
        if (c < 2) { issue_B(sbase, tid, c + 2, s); CP_COMMIT(); }
    }

    // epilogue: relu + store (32x64 per warp)
#pragma unroll
    for (int mi = 0; mi < 2; mi++) {
        int r0 = row0 + warp_m * 32 + mi * 16 + (lane >> 2);
#pragma unroll
        for (int ni = 0; ni < 8; ni++) {
            int col = warp_n * 64 + ni * 8 + (lane & 3) * 2;
            if (r0 < N_NODES) {
                float2 v;
                v.x = fmaxf(acc[mi][ni][0], 0.f);
                v.y = fmaxf(acc[mi][ni][1], 0.f);
                *(float2*)(out + (size_t)r0 * DIM + col) = v;
            }
            if (r0 + 8 < N_NODES) {
                float2 v;
                v.x = fmaxf(acc[mi][ni][2], 0.f);
                v.y = fmaxf(acc[mi][ni][3], 0.f);
                *(float2*)(out + (size_t)(r0 + 8) * DIM + col) = v;
            }
        }
    }
}

// ---------------------------------------------------------------------------
// Launcher
// ---------------------------------------------------------------------------
extern "C" void kernel_launch(void* const* d_in, const int* in_sizes, int n_in,
                              void* d_out, int out_size)
{
    (void)in_sizes; (void)n_in; (void)out_size;

    const float* h          = (const float*)d_in[0];
    const float* norm       = (const float*)d_in[1];
    const float* rel_emb    = (const float*)d_in[2];
    const float* W_neighbor = (const float*)d_in[3];
    const float* loop_w     = (const float*)d_in[4];
    const int*   edge_src   = (const int*)d_in[5];
    const int*   edge_dst   = (const int*)d_in[6];
    const int*   edge_type  = (const int*)d_in[7];
    float*       out        = (float*)d_out;

    init_kernel<<<ZERO_BLOCKS + 128, 256>>>(W_neighbor, loop_w);
    {
        long long total = (long long)N_EDGES * 32;
        scatter_edges_kernel<<<(int)((total + 255) / 256), 256>>>(h, rel_emb, edge_src, edge_dst, edge_type);
    }
    {
        static bool attr_set = false;
        if (!attr_set) {
            cudaFuncSetAttribute(gemm_fused_kernel,
                                 cudaFuncAttributeMaxDynamicSharedMemorySize, SM_TOTAL);
            attr_set = true;
        }
        gemm_fused_kernel<<<NTILES, 256, SM_TOTAL>>>(h, norm, out);
    }
}

// round 9
// speedup vs baseline: 3.3719x; 1.8063x over previous
#include <cuda_runtime.h>
#include <cuda_fp16.h>
#include <cstdint>

#define N_NODES 50000
#define N_EDGES 600000
#define N_RELS  500
#define DIM     128
#define M_PAD   50048
#define NTILES  391          // ceil(50000/128)

typedef unsigned int u32;
typedef unsigned short u16;

// ---------------------------------------------------------------------------
// Device scratch (all fp16)
// ---------------------------------------------------------------------------
__device__ __align__(16) u16 g_S16[(size_t)M_PAD * DIM];      // fp16 scatter accumulator
__device__ __align__(16) u16 g_h16[(size_t)M_PAD * DIM];      // fp16 h (padded w/ zeros)
__device__ __align__(16) u16 g_rel16[N_RELS * DIM];           // fp16 rel_emb
__device__ __align__(16) u16 g_B[256 * DIM];                  // B=[Wn;Wl] fp16 [K=256][N=128]

__device__ __forceinline__ u32 pack_h2(float lo, float hi) {
    u32 r;
    asm("cvt.rn.f16x2.f32 %0, %1, %2;" : "=r"(r) : "f"(hi), "f"(lo));
    return r;
}

// ---------------------------------------------------------------------------
// Kernel 1: unified init (grid-stride):
//   [0, T0)        zero g_S16
//   [T0, T1)       h -> fp16 (zero-pad rows >= N_NODES)
//   [T1, T2)       rel_emb -> fp16
//   [T2, T3)       B = [Wn; Wl] -> fp16
// Each item handles 8 elements (one uint4 of halves).
// ---------------------------------------------------------------------------
#define IT0 (N_NODES * DIM / 8)
#define IT1 (IT0 + M_PAD * DIM / 8)
#define IT2 (IT1 + N_RELS * DIM / 8)
#define IT3 (IT2 + 256 * DIM / 8)

__global__ void __launch_bounds__(256) init_kernel(
    const float* __restrict__ h,
    const float* __restrict__ rel_emb,
    const float* __restrict__ W_neighbor,
    const float* __restrict__ loop_weight)
{
    for (int i = blockIdx.x * 256 + threadIdx.x; i < IT3; i += gridDim.x * 256) {
        if (i < IT0) {
            ((uint4*)g_S16)[i] = make_uint4(0, 0, 0, 0);
        } else if (i < IT1) {
            int j   = i - IT0;
            int row = j >> 4;
            int sg  = j & 15;
            uint4 o = make_uint4(0, 0, 0, 0);
            if (row < N_NODES) {
                const float4* src = (const float4*)(h + (size_t)row * DIM + sg * 8);
                float4 a = src[0], b = src[1];
                o.x = pack_h2(a.x, a.y); o.y = pack_h2(a.z, a.w);
                o.z = pack_h2(b.x, b.y); o.w = pack_h2(b.z, b.w);
            }
            ((uint4*)g_h16)[j] = o;
        } else if (i < IT2) {
            int j = i - IT1;
            const float4* src = (const float4*)(rel_emb + (size_t)j * 8);
            float4 a = src[0], b = src[1];
            uint4 o;
            o.x = pack_h2(a.x, a.y); o.y = pack_h2(a.z, a.w);
            o.z = pack_h2(b.x, b.y); o.w = pack_h2(b.z, b.w);
            ((uint4*)g_rel16)[j] = o;
        } else {
            int j = i - IT2;                 // < 4096
            int k = j >> 4;
            int sg = j & 15;
            const float* src = (k < 128) ? (W_neighbor + (size_t)k * DIM + sg * 8)
                                         : (loop_weight + (size_t)(k - 128) * DIM + sg * 8);
            float4 a = ((const float4*)src)[0], b = ((const float4*)src)[1];
            uint4 o;
            o.x = pack_h2(a.x, a.y); o.y = pack_h2(a.z, a.w);
            o.z = pack_h2(b.x, b.y); o.w = pack_h2(b.z, b.w);
            ((uint4*)g_B)[j] = o;
        }
    }
}

// ---------------------------------------------------------------------------
// Kernel 2: fp16 edge scatter.  16 lanes per edge (one warp = 2 edges).
//   S16[dst] += h16[src] + rel16[type]      (fp16x2 adds + v4.f16x2 RED)
// ---------------------------------------------------------------------------
__global__ void __launch_bounds__(256) scatter_edges_kernel(
    const int* __restrict__ edge_src,
    const int* __restrict__ edge_dst,
    const int* __restrict__ edge_type)
{
    int w    = (int)((blockIdx.x * (unsigned)blockDim.x + threadIdx.x) >> 5);
    int lane = threadIdx.x & 31;
    int e    = w * 2 + (lane >> 4);
    if (e >= N_EDGES) return;
    int l16 = lane & 15;

    int s = __ldg(edge_src  + e);
    int d = __ldg(edge_dst  + e);
    int t = __ldg(edge_type + e);

    const uint4 hv = *(const uint4*)(g_h16   + (size_t)s * DIM + l16 * 8);
    const uint4 rv = *(const uint4*)(g_rel16 + (size_t)t * DIM + l16 * 8);

    u32 m0, m1, m2, m3;
    asm("add.rn.f16x2 %0, %1, %2;" : "=r"(m0) : "r"(hv.x), "r"(rv.x));
    asm("add.rn.f16x2 %0, %1, %2;" : "=r"(m1) : "r"(hv.y), "r"(rv.y));
    asm("add.rn.f16x2 %0, %1, %2;" : "=r"(m2) : "r"(hv.z), "r"(rv.z));
    asm("add.rn.f16x2 %0, %1, %2;" : "=r"(m3) : "r"(hv.w), "r"(rv.w));

    u16* outp = g_S16 + (size_t)d * DIM + l16 * 8;
    asm volatile("red.global.add.noftz.v4.f16x2 [%0], {%1, %2, %3, %4};"
                 :: "l"(outp), "r"(m0), "r"(m1), "r"(m2), "r"(m3) : "memory");
}

// ---------------------------------------------------------------------------
// Kernel 3: fused GEMM, fp16.
//   out = relu( [norm*S | h] @ [Wn; Wl] )
// CTA 256 thr / 8 warps, tile 128x128, K=256 in 4 chunks of 64; warp 32x64.
// A chunks 0-1: LDG fp16 S + fp32 norm scale + STS.  A chunks 2-3 + B: cp.async.
// ---------------------------------------------------------------------------
#define A_STRIDE 144
#define B_STRIDE 272
#define OFF_A(s) ((s) * 18432)
#define OFF_B(s) (36864 + (s) * 17408)
#define SM_TOTAL 71680

__device__ __forceinline__ void ldsm4(u32* r, u32 addr) {
    asm volatile("ldmatrix.sync.aligned.m8n8.x4.shared.b16 {%0,%1,%2,%3}, [%4];"
                 : "=r"(r[0]), "=r"(r[1]), "=r"(r[2]), "=r"(r[3]) : "r"(addr));
}
__device__ __forceinline__ void ldsm4t(u32* r, u32 addr) {
    asm volatile("ldmatrix.sync.aligned.m8n8.x4.trans.shared.b16 {%0,%1,%2,%3}, [%4];"
                 : "=r"(r[0]), "=r"(r[1]), "=r"(r[2]), "=r"(r[3]) : "r"(addr));
}
__device__ __forceinline__ void mma16816(float* d, const u32* a, u32 b0, u32 b1) {
    asm volatile("mma.sync.aligned.m16n8k16.row.col.f32.f16.f16.f32 "
                 "{%0,%1,%2,%3}, {%4,%5,%6,%7}, {%8,%9}, {%0,%1,%2,%3};"
                 : "+f"(d[0]), "+f"(d[1]), "+f"(d[2]), "+f"(d[3])
                 : "r"(a[0]), "r"(a[1]), "r"(a[2]), "r"(a[3]), "r"(b0), "r"(b1));
}
__device__ __forceinline__ void cp16(u32 dst, const void* src) {
    asm volatile("cp.async.cg.shared.global [%0], [%1], 16;" :: "r"(dst), "l"(src) : "memory");
}
#define CP_COMMIT() asm volatile("cp.async.commit_group;" ::: "memory")

// stage A chunk c (c in {0,1}): fp16 S read, fp32 norm scale, repack, STS
__device__ __forceinline__ void stage_A_S(const float* __restrict__ norm,
                                          int row0, int c, int tid,
                                          char* smem, u32 a_off)
{
    int row  = tid >> 1;
    int half = tid & 1;
    int gr   = row0 + row;
    bool valid = (gr < N_NODES);
    float sc = valid ? __ldg(norm + gr) : 0.f;
    const uint4* src = (const uint4*)(g_S16 + (size_t)gr * DIM + c * 64 + half * 32);
    u32 ob = a_off + (u32)(row * A_STRIDE + half * 64);
#pragma unroll
    for (int p = 0; p < 4; p++) {
        uint4 o = make_uint4(0, 0, 0, 0);
        if (valid) {
            uint4 v = src[p];
            const u32* vv = (const u32*)&v;
            u32* oo = (u32*)&o;
#pragma unroll
            for (int q = 0; q < 4; q++) {
                float2 f = __half22float2(*(const __half2*)&vv[q]);
                oo[q] = pack_h2(f.x * sc, f.y * sc);
            }
        }
        *(uint4*)(smem + ob + p * 16) = o;
    }
}

// cp.async B chunk c into stage s
__device__ __forceinline__ void issue_B(u32 sbase, int tid, int c, int s)
{
    u32 bb = sbase + OFF_B(s);
#pragma unroll
    for (int it = 0; it < 4; it++) {
        int i  = tid + it * 256;           // < 1024
        int r  = i >> 4;
        int sg = i & 15;
        cp16(bb + (u32)(r * B_STRIDE + sg * 16),
             (const char*)g_B + (size_t)(c * 64 + r) * 256 + sg * 16);
    }
}

// cp.async A chunk c (c in {2,3}) from padded g_h16 into stage s
__device__ __forceinline__ void issue_Ah(u32 sbase, int tid, int row0, int c, int s)
{
    u32 ab = sbase + OFF_A(s);
#pragma unroll
    for (int it = 0; it < 4; it++) {
        int i  = tid + it * 256;           // < 1024
        int r  = i >> 3;
        int sg = i & 7;
        cp16(ab + (u32)(r * A_STRIDE + sg * 16),
             (const char*)g_h16 + ((size_t)(row0 + r) * DIM + (c - 2) * 64) * 2 + sg * 16);
    }
}

__global__ void __launch_bounds__(256, 2) gemm_fused_kernel(
    const float* __restrict__ norm,
    float* __restrict__ out)
{
    extern __shared__ char smem[];
    u32 sbase;
    asm("{ .reg .u64 t; cvta.to.shared.u64 t, %1; cvt.u32.u64 %0, t; }"
        : "=r"(sbase) : "l"(smem));

    const int tid    = threadIdx.x;
    const int wid    = tid >> 5;
    const int lane   = tid & 31;
    const int warp_m = wid & 3;
    const int warp_n = wid >> 2;
    const int row0   = blockIdx.x * 128;

    issue_B(sbase, tid, 0, 0);
    CP_COMMIT();
    issue_B(sbase, tid, 1, 1);
    CP_COMMIT();
    stage_A_S(norm, row0, 0, tid, smem, OFF_A(0));

    float acc[2][8][4];
#pragma unroll
    for (int mi = 0; mi < 2; mi++)
#pragma unroll
        for (int ni = 0; ni < 8; ni++)
#pragma unroll
            for (int q = 0; q < 4; q++) acc[mi][ni][q] = 0.f;

#pragma unroll
    for (int c = 0; c < 4; c++) {
        const int s = c & 1;
        if (c < 3) asm volatile("cp.async.wait_group 1;" ::: "memory");
        else       asm volatile("cp.async.wait_group 0;" ::: "memory");
        __syncthreads();

        const u32 a_sm = sbase + OFF_A(s);
        const u32 b_sm = sbase + OFF_B(s);
#pragma unroll
        for (int k16 = 0; k16 < 4; k16++) {
            u32 bh[4][4];
#pragma unroll
            for (int ng = 0; ng < 4; ng++) {
                u32 baddr = b_sm
                          + (u32)((k16 * 16 + (lane & 15)) * B_STRIDE)
                          + (u32)((warp_n * 64 + ng * 16 + (lane >> 4) * 8) * 2);
                ldsm4t(bh[ng], baddr);
            }
#pragma unroll
            for (int mi = 0; mi < 2; mi++) {
                u32 aaddr = a_sm
                          + (u32)((warp_m * 32 + mi * 16 + (lane & 15)) * A_STRIDE)
                          + (u32)(k16 * 32 + (lane >> 4) * 16);
                u32 ah[4];
                ldsm4(ah, aaddr);
#pragma unroll
                for (int ni = 0; ni < 8; ni++) {
                    int ng = ni >> 1;
                    int hf = (ni & 1) * 2;
                    mma16816(acc[mi][ni], ah, bh[ng][hf], bh[ng][hf + 1]);
                }
            }
        }

        // stage next S chunk (only c==0 -> chunk 1)
        if (c == 0) stage_A_S(norm, row0, 1, tid, smem, OFF_A(1));
        __syncthreads();
        // refill freed buffers with chunk c+2 (B + A via cp.async)
        if (c < 2) {
            issue_B(sbase, tid, c + 2, s);
            issue_Ah(sbase, tid, row0, c + 2, s);
            CP_COMMIT();
        }
    }

    // epilogue: relu + store (32x64 per warp)
#pragma unroll
    for (int mi = 0; mi < 2; mi++) {
        int r0 = row0 + warp_m * 32 + mi * 16 + (lane >> 2);
#pragma unroll
        for (int ni = 0; ni < 8; ni++) {
            int col = warp_n * 64 + ni * 8 + (lane & 3) * 2;
            if (r0 < N_NODES) {
                float2 v;
                v.x = fmaxf(acc[mi][ni][0], 0.f);
                v.y = fmaxf(acc[mi][ni][1], 0.f);
                *(float2*)(out + (size_t)r0 * DIM + col) = v;
            }
            if (r0 + 8 < N_NODES) {
                float2 v;
                v.x = fmaxf(acc[mi][ni][2], 0.f);
                v.y = fmaxf(acc[mi][ni][3], 0.f);
                *(float2*)(out + (size_t)(r0 + 8) * DIM + col) = v;
            }
        }
    }
}

// ---------------------------------------------------------------------------
// Launcher
// ---------------------------------------------------------------------------
extern "C" void kernel_launch(void* const* d_in, const int* in_sizes, int n_in,
                              void* d_out, int out_size)
{
    (void)in_sizes; (void)n_in; (void)out_size;

    const float* h          = (const float*)d_in[0];
    const float* norm       = (const float*)d_in[1];
    const float* rel_emb    = (const float*)d_in[2];
    const float* W_neighbor = (const float*)d_in[3];
    const float* loop_w     = (const float*)d_in[4];
    const int*   edge_src   = (const int*)d_in[5];
    const int*   edge_dst   = (const int*)d_in[6];
    const int*   edge_type  = (const int*)d_in[7];
    float*       out        = (float*)d_out;

    init_kernel<<<1184, 256>>>(h, rel_emb, W_neighbor, loop_w);
    {
        // one warp per 2 edges
        long long warps = (N_EDGES + 1) / 2;
        long long threads = warps * 32;
        scatter_edges_kernel<<<(int)((threads + 255) / 256), 256>>>(edge_src, edge_dst, edge_type);
    }
    {
        static bool attr_set = false;
        if (!attr_set) {
            cudaFuncSetAttribute(gemm_fused_kernel,
                                 cudaFuncAttributeMaxDynamicSharedMemorySize, SM_TOTAL);
            attr_set = true;
        }
        gemm_fused_kernel<<<NTILES, 256, SM_TOTAL>>>(norm, out);
    }
}

// round 10
// speedup vs baseline: 3.4890x; 1.0347x over previous
#include <cuda_runtime.h>
#include <cuda_fp16.h>
#include <cstdint>

#define N_NODES 50000
#define N_EDGES 600000
#define N_RELS  500
#define DIM     128
#define M_PAD   50048
#define NTILES  391          // ceil(50000/128)

typedef unsigned int u32;
typedef unsigned short u16;

// ---------------------------------------------------------------------------
// Device scratch (all fp16)
// ---------------------------------------------------------------------------
__device__ __align__(16) u16 g_S16[(size_t)M_PAD * DIM];      // fp16 scatter accumulator
__device__ __align__(16) u16 g_h16[(size_t)M_PAD * DIM];      // fp16 h (padded w/ zeros)
__device__ __align__(16) u16 g_rel16[N_RELS * DIM];           // fp16 rel_emb
__device__ __align__(16) u16 g_B[256 * DIM];                  // B=[Wn;Wl] fp16 [K=256][N=128]

__device__ __forceinline__ u32 pack_h2(float lo, float hi) {
    u32 r;
    asm("cvt.rn.f16x2.f32 %0, %1, %2;" : "=r"(r) : "f"(hi), "f"(lo));
    return r;
}

// ---------------------------------------------------------------------------
// Kernel 1: unified init (grid-stride)
// ---------------------------------------------------------------------------
#define IT0 (N_NODES * DIM / 8)
#define IT1 (IT0 + M_PAD * DIM / 8)
#define IT2 (IT1 + N_RELS * DIM / 8)
#define IT3 (IT2 + 256 * DIM / 8)

__global__ void __launch_bounds__(256) init_kernel(
    const float* __restrict__ h,
    const float* __restrict__ rel_emb,
    const float* __restrict__ W_neighbor,
    const float* __restrict__ loop_weight)
{
    for (int i = blockIdx.x * 256 + threadIdx.x; i < IT3; i += gridDim.x * 256) {
        if (i < IT0) {
            ((uint4*)g_S16)[i] = make_uint4(0, 0, 0, 0);
        } else if (i < IT1) {
            int j   = i - IT0;
            int row = j >> 4;
            int sg  = j & 15;
            uint4 o = make_uint4(0, 0, 0, 0);
            if (row < N_NODES) {
                const float4* src = (const float4*)(h + (size_t)row * DIM + sg * 8);
                float4 a = src[0], b = src[1];
                o.x = pack_h2(a.x, a.y); o.y = pack_h2(a.z, a.w);
                o.z = pack_h2(b.x, b.y); o.w = pack_h2(b.z, b.w);
            }
            ((uint4*)g_h16)[j] = o;
        } else if (i < IT2) {
            int j = i - IT1;
            const float4* src = (const float4*)(rel_emb + (size_t)j * 8);
            float4 a = src[0], b = src[1];
            uint4 o;
            o.x = pack_h2(a.x, a.y); o.y = pack_h2(a.z, a.w);
            o.z = pack_h2(b.x, b.y); o.w = pack_h2(b.z, b.w);
            ((uint4*)g_rel16)[j] = o;
        } else {
            int j = i - IT2;                 // < 4096
            int k = j >> 4;
            int sg = j & 15;
            const float* src = (k < 128) ? (W_neighbor + (size_t)k * DIM + sg * 8)
                                         : (loop_weight + (size_t)(k - 128) * DIM + sg * 8);
            float4 a = ((const float4*)src)[0], b = ((const float4*)src)[1];
            uint4 o;
            o.x = pack_h2(a.x, a.y); o.y = pack_h2(a.z, a.w);
            o.z = pack_h2(b.x, b.y); o.w = pack_h2(b.z, b.w);
            ((uint4*)g_B)[j] = o;
        }
    }
}

// ---------------------------------------------------------------------------
// Kernel 2: fp16 edge scatter.  16 lanes per edge (one warp = 2 edges).
// ---------------------------------------------------------------------------
__global__ void __launch_bounds__(256) scatter_edges_kernel(
    const int* __restrict__ edge_src,
    const int* __restrict__ edge_dst,
    const int* __restrict__ edge_type)
{
    int w    = (int)((blockIdx.x * (unsigned)blockDim.x + threadIdx.x) >> 5);
    int lane = threadIdx.x & 31;
    int e    = w * 2 + (lane >> 4);
    if (e >= N_EDGES) return;
    int l16 = lane & 15;

    int s = __ldg(edge_src  + e);
    int d = __ldg(edge_dst  + e);
    int t = __ldg(edge_type + e);

    const uint4 hv = *(const uint4*)(g_h16   + (size_t)s * DIM + l16 * 8);
    const uint4 rv = *(const uint4*)(g_rel16 + (size_t)t * DIM + l16 * 8);

    u32 m0, m1, m2, m3;
    asm("add.rn.f16x2 %0, %1, %2;" : "=r"(m0) : "r"(hv.x), "r"(rv.x));
    asm("add.rn.f16x2 %0, %1, %2;" : "=r"(m1) : "r"(hv.y), "r"(rv.y));
    asm("add.rn.f16x2 %0, %1, %2;" : "=r"(m2) : "r"(hv.z), "r"(rv.z));
    asm("add.rn.f16x2 %0, %1, %2;" : "=r"(m3) : "r"(hv.w), "r"(rv.w));

    u16* outp = g_S16 + (size_t)d * DIM + l16 * 8;
    asm volatile("red.global.add.noftz.v4.f16x2 [%0], {%1, %2, %3, %4};"
                 :: "l"(outp), "r"(m0), "r"(m1), "r"(m2), "r"(m3) : "memory");
}

// ---------------------------------------------------------------------------
// Kernel 3: fused GEMM, fp16, pure cp.async staging.
//   out = relu( norm .* (S @ Wn) + h @ Wl )
// K chunks 0-1 = S, 2-3 = h.  norm applied in fp32 to accumulators between
// chunk 1 and chunk 2.  CTA 256 thr / 8 warps, tile 128x128, warp 32x64.
// ---------------------------------------------------------------------------
#define A_STRIDE 144
#define B_STRIDE 272
#define OFF_A(s) ((s) * 18432)
#define OFF_B(s) (36864 + (s) * 17408)
#define SM_TOTAL 71680

__device__ __forceinline__ void ldsm4(u32* r, u32 addr) {
    asm volatile("ldmatrix.sync.aligned.m8n8.x4.shared.b16 {%0,%1,%2,%3}, [%4];"
                 : "=r"(r[0]), "=r"(r[1]), "=r"(r[2]), "=r"(r[3]) : "r"(addr));
}
__device__ __forceinline__ void ldsm4t(u32* r, u32 addr) {
    asm volatile("ldmatrix.sync.aligned.m8n8.x4.trans.shared.b16 {%0,%1,%2,%3}, [%4];"
                 : "=r"(r[0]), "=r"(r[1]), "=r"(r[2]), "=r"(r[3]) : "r"(addr));
}
__device__ __forceinline__ void mma16816(float* d, const u32* a, u32 b0, u32 b1) {
    asm volatile("mma.sync.aligned.m16n8k16.row.col.f32.f16.f16.f32 "
                 "{%0,%1,%2,%3}, {%4,%5,%6,%7}, {%8,%9}, {%0,%1,%2,%3};"
                 : "+f"(d[0]), "+f"(d[1]), "+f"(d[2]), "+f"(d[3])
                 : "r"(a[0]), "r"(a[1]), "r"(a[2]), "r"(a[3]), "r"(b0), "r"(b1));
}
__device__ __forceinline__ void cp16(u32 dst, const void* src) {
    asm volatile("cp.async.cg.shared.global [%0], [%1], 16;" :: "r"(dst), "l"(src) : "memory");
}
#define CP_COMMIT() asm volatile("cp.async.commit_group;" ::: "memory")

// cp.async A+B chunk c into stage s.  A source: S16 for c<2, h16 for c>=2.
__device__ __forceinline__ void issue_chunk(u32 sbase, int tid, int row0, int c, int s)
{
    const u16* asrc = (c < 2) ? g_S16 : g_h16;
    int koff = (c & 1) * 64;
    u32 ab = sbase + OFF_A(s);
#pragma unroll
    for (int it = 0; it < 4; it++) {
        int i  = tid + it * 256;           // < 1024
        int r  = i >> 3;
        int sg = i & 7;
        cp16(ab + (u32)(r * A_STRIDE + sg * 16),
             (const char*)(asrc + (size_t)(row0 + r) * DIM + koff) + sg * 16);
    }
    u32 bb = sbase + OFF_B(s);
#pragma unroll
    for (int it = 0; it < 4; it++) {
        int i  = tid + it * 256;           // < 1024
        int r  = i >> 4;
        int sg = i & 15;
        cp16(bb + (u32)(r * B_STRIDE + sg * 16),
             (const char*)g_B + (size_t)(c * 64 + r) * 256 + sg * 16);
    }
}

__global__ void __launch_bounds__(256, 2) gemm_fused_kernel(
    const float* __restrict__ norm,
    float* __restrict__ out)
{
    extern __shared__ char smem[];
    u32 sbase;
    asm("{ .reg .u64 t; cvta.to.shared.u64 t, %1; cvt.u32.u64 %0, t; }"
        : "=r"(sbase) : "l"(smem));

    const int tid    = threadIdx.x;
    const int wid    = tid >> 5;
    const int lane   = tid & 31;
    const int warp_m = wid & 3;
    const int warp_n = wid >> 2;
    const int row0   = blockIdx.x * 128;

    // per-thread norm values for the two rows each mi owns
    float nrm[2][2];
#pragma unroll
    for (int mi = 0; mi < 2; mi++) {
        int r0 = row0 + warp_m * 32 + mi * 16 + (lane >> 2);
        nrm[mi][0] = (r0     < N_NODES) ? __ldg(norm + r0)     : 0.f;
        nrm[mi][1] = (r0 + 8 < N_NODES) ? __ldg(norm + r0 + 8) : 0.f;
    }

    issue_chunk(sbase, tid, row0, 0, 0);
    CP_COMMIT();
    issue_chunk(sbase, tid, row0, 1, 1);
    CP_COMMIT();

    float acc[2][8][4];
#pragma unroll
    for (int mi = 0; mi < 2; mi++)
#pragma unroll
        for (int ni = 0; ni < 8; ni++)
#pragma unroll
            for (int q = 0; q < 4; q++) acc[mi][ni][q] = 0.f;

#pragma unroll
    for (int c = 0; c < 4; c++) {
        const int s = c & 1;
        if (c < 3) asm volatile("cp.async.wait_group 1;" ::: "memory");
        else       asm volatile("cp.async.wait_group 0;" ::: "memory");
        __syncthreads();

        const u32 a_sm = sbase + OFF_A(s);
        const u32 b_sm = sbase + OFF_B(s);
#pragma unroll
        for (int k16 = 0; k16 < 4; k16++) {
            u32 bh[4][4];
#pragma unroll
            for (int ng = 0; ng < 4; ng++) {
                u32 baddr = b_sm
                          + (u32)((k16 * 16 + (lane & 15)) * B_STRIDE)
                          + (u32)((warp_n * 64 + ng * 16 + (lane >> 4) * 8) * 2);
                ldsm4t(bh[ng], baddr);
            }
#pragma unroll
            for (int mi = 0; mi < 2; mi++) {
                u32 aaddr = a_sm
                          + (u32)((warp_m * 32 + mi * 16 + (lane & 15)) * A_STRIDE)
                          + (u32)(k16 * 32 + (lane >> 4) * 16);
                u32 ah[4];
                ldsm4(ah, aaddr);
#pragma unroll
                for (int ni = 0; ni < 8; ni++) {
                    int ng = ni >> 1;
                    int hf = (ni & 1) * 2;
                    mma16816(acc[mi][ni], ah, bh[ng][hf], bh[ng][hf + 1]);
                }
            }
        }

        // after the S half (chunks 0-1): scale accumulators by norm (fp32)
        if (c == 1) {
#pragma unroll
            for (int mi = 0; mi < 2; mi++)
#pragma unroll
                for (int ni = 0; ni < 8; ni++) {
                    acc[mi][ni][0] *= nrm[mi][0];
                    acc[mi][ni][1] *= nrm[mi][0];
                    acc[mi][ni][2] *= nrm[mi][1];
                    acc[mi][ni][3] *= nrm[mi][1];
                }
        }

        __syncthreads();
        if (c < 2) { issue_chunk(sbase, tid, row0, c + 2, s); CP_COMMIT(); }
    }

    // epilogue: relu + store (32x64 per warp)
#pragma unroll
    for (int mi = 0; mi < 2; mi++) {
        int r0 = row0 + warp_m * 32 + mi * 16 + (lane >> 2);
#pragma unroll
        for (int ni = 0; ni < 8; ni++) {
            int col = warp_n * 64 + ni * 8 + (lane & 3) * 2;
            if (r0 < N_NODES) {
                float2 v;
                v.x = fmaxf(acc[mi][ni][0], 0.f);
                v.y = fmaxf(acc[mi][ni][1], 0.f);
                *(float2*)(out + (size_t)r0 * DIM + col) = v;
            }
            if (r0 + 8 < N_NODES) {
                float2 v;
                v.x = fmaxf(acc[mi][ni][2], 0.f);
                v.y = fmaxf(acc[mi][ni][3], 0.f);
                *(float2*)(out + (size_t)(r0 + 8) * DIM + col) = v;
            }
        }
    }
}

// ---------------------------------------------------------------------------
// Launcher
// ---------------------------------------------------------------------------
extern "C" void kernel_launch(void* const* d_in, const int* in_sizes, int n_in,
                              void* d_out, int out_size)
{
    (void)in_sizes; (void)n_in; (void)out_size;

    const float* h          = (const float*)d_in[0];
    const float* norm       = (const float*)d_in[1];
    const float* rel_emb    = (const float*)d_in[2];
    const float* W_neighbor = (const float*)d_in[3];
    const float* loop_w     = (const float*)d_in[4];
    const int*   edge_src   = (const int*)d_in[5];
    const int*   edge_dst   = (const int*)d_in[6];
    const int*   edge_type  = (const int*)d_in[7];
    float*       out        = (float*)d_out;

    init_kernel<<<1184, 256>>>(h, rel_emb, W_neighbor, loop_w);
    {
        long long warps = (N_EDGES + 1) / 2;
        long long threads = warps * 32;
        scatter_edges_kernel<<<(int)((threads + 255) / 256), 256>>>(edge_src, edge_dst, edge_type);
    }
    {
        static bool attr_set = false;
        if (!attr_set) {
            cudaFuncSetAttribute(gemm_fused_kernel,
                                 cudaFuncAttributeMaxDynamicSharedMemorySize, SM_TOTAL);
            attr_set = true;
        }
        gemm_fused_kernel<<<NTILES, 256, SM_TOTAL>>>(norm, out);
    }
}